// round 3
// baseline (speedup 1.0000x reference)
#include <cuda_runtime.h>
#include <math.h>
#include <stdint.h>

// Problem constants
#define LL   2048
#define BBATCH 4
#define EE   512
#define HH   8
#define HDD  64
#define HIDD 2048
#define TT   (LL*BBATCH)   // 8192 tokens

// ---------------- scratch (no allocations allowed) ----------------
__device__ float g_x0[TT*EE];        // x + pe
__device__ float g_qkv[TT*3*EE];     // qkv projection
__device__ float g_att[TT*EE];       // attention out; later reused as ff out
__device__ float g_proj[TT*EE];      // out-proj result
__device__ float g_x1[TT*EE];        // after first LN
__device__ float g_h[TT*HIDD];       // ffn hidden

// ---------------- kernel 1: positional-encoding add ----------------
__global__ void pe_add_kernel(const float* __restrict__ x, float* __restrict__ out) {
    int i = blockIdx.x * blockDim.x + threadIdx.x;
    if (i >= TT*EE) return;
    int e = i & (EE - 1);
    int b = (i / EE) & (BBATCH - 1);
    // even e: sin((b+1)*10000^(-e/E)); odd e: cos((b+1)*10000^(-(e+1)/E))
    float ef = (e & 1) ? (float)(e + 1) : (float)e;
    // 10000^(-ef/512) = exp(-ef * ln(10000)/512)
    float freq = expf(-ef * (9.210340371976184f / 512.0f));
    float arg = (float)(b + 1) * freq;
    float pe = (e & 1) ? cosf(arg) : sinf(arg);
    out[i] = x[i] + pe;
}

// ---------------- kernel 2: SGEMM  C[M,N] = A[M,K] * W[N,K]^T + bias (+GELU) ----
// BM=BN=128, BK=8, 256 threads, 8x8 per-thread tile. M,N multiples of 128, K of 8.
__device__ __forceinline__ float gelu_exact(float v) {
    return 0.5f * v * (1.0f + erff(v * 0.70710678118654752f));
}

template <int GELU>
__global__ void __launch_bounds__(256)
sgemm_nt(const float* __restrict__ A, const float* __restrict__ W,
         const float* __restrict__ bias, float* __restrict__ C,
         int M, int N, int K) {
    __shared__ float As[8][128];
    __shared__ float Bs[8][128];

    int tid = threadIdx.x;
    int tx = tid & 15;          // 0..15 -> col group
    int ty = tid >> 4;          // 0..15 -> row group
    int rowBase = ty * 8;
    int colBase = tx * 8;
    int bRow = blockIdx.y * 128;
    int bCol = blockIdx.x * 128;

    int lr = tid >> 1;          // 0..127: tile row to load
    int lc = (tid & 1) * 4;     // 0 or 4: k-offset (float4)

    const float* Ag = A + (size_t)(bRow + lr) * K + lc;
    const float* Wg = W + (size_t)(bCol + lr) * K + lc;

    float acc[8][8];
#pragma unroll
    for (int i = 0; i < 8; i++)
#pragma unroll
        for (int j = 0; j < 8; j++) acc[i][j] = 0.0f;

    float4 a_next = *(const float4*)Ag;
    float4 b_next = *(const float4*)Wg;

    for (int k0 = 0; k0 < K; k0 += 8) {
        As[lc + 0][lr] = a_next.x; As[lc + 1][lr] = a_next.y;
        As[lc + 2][lr] = a_next.z; As[lc + 3][lr] = a_next.w;
        Bs[lc + 0][lr] = b_next.x; Bs[lc + 1][lr] = b_next.y;
        Bs[lc + 2][lr] = b_next.z; Bs[lc + 3][lr] = b_next.w;
        __syncthreads();

        if (k0 + 8 < K) {
            a_next = *(const float4*)(Ag + k0 + 8);
            b_next = *(const float4*)(Wg + k0 + 8);
        }

#pragma unroll
        for (int kk = 0; kk < 8; kk++) {
            float4 a0 = *(const float4*)&As[kk][rowBase];
            float4 a1 = *(const float4*)&As[kk][rowBase + 4];
            float4 b0 = *(const float4*)&Bs[kk][colBase];
            float4 b1 = *(const float4*)&Bs[kk][colBase + 4];
            float av[8] = {a0.x, a0.y, a0.z, a0.w, a1.x, a1.y, a1.z, a1.w};
            float bv[8] = {b0.x, b0.y, b0.z, b0.w, b1.x, b1.y, b1.z, b1.w};
#pragma unroll
            for (int i = 0; i < 8; i++)
#pragma unroll
                for (int j = 0; j < 8; j++)
                    acc[i][j] = fmaf(av[i], bv[j], acc[i][j]);
        }
        __syncthreads();
    }

    float bb[8];
#pragma unroll
    for (int j = 0; j < 8; j++) bb[j] = bias[bCol + colBase + j];

#pragma unroll
    for (int i = 0; i < 8; i++) {
        size_t row = (size_t)(bRow + rowBase + i);
        float v[8];
#pragma unroll
        for (int j = 0; j < 8; j++) {
            float t = acc[i][j] + bb[j];
            v[j] = GELU ? gelu_exact(t) : t;
        }
        float4 o0 = {v[0], v[1], v[2], v[3]};
        float4 o1 = {v[4], v[5], v[6], v[7]};
        *(float4*)&C[row * N + bCol + colBase]     = o0;
        *(float4*)&C[row * N + bCol + colBase + 4] = o1;
    }
}

// ---------------- kernel 3: flash attention (fp32, no mask) ----------------
// grid: (L/64, B*H). block: 256 threads (16x16), each owns a 4x4 tile.
__global__ void __launch_bounds__(256)
flash_attn(const float* __restrict__ qkv, float* __restrict__ out) {
    __shared__ float Qs[64][64];   // Q tile, [row][d]
    __shared__ float Ks[64][64];   // K tile transposed [d][key]; reused as P [row][key]
    __shared__ float Vs[64][64];   // V tile [key][d]

    int tid = threadIdx.x;
    int tx = tid & 15;
    int ty = tid >> 4;
    int q0 = blockIdx.x * 64;
    int bh = blockIdx.y;
    int b = bh >> 3;
    int h = bh & 7;
    int qoff = h * 64;
    int koff = 512 + h * 64;
    int voff = 1024 + h * 64;

    // load Q tile (vectorized)
    for (int i = tid; i < 64 * 16; i += 256) {
        int r = i >> 4;
        int c4 = (i & 15) * 4;
        float4 v = *(const float4*)&qkv[((size_t)((q0 + r) * BBATCH + b)) * 1536 + qoff + c4];
        *(float4*)&Qs[r][c4] = v;
    }

    float m_i[4], l_i[4], o[4][4];
#pragma unroll
    for (int i = 0; i < 4; i++) {
        m_i[i] = -1e30f; l_i[i] = 0.0f;
#pragma unroll
        for (int j = 0; j < 4; j++) o[i][j] = 0.0f;
    }
    float* Ps = &Ks[0][0];

    for (int kt = 0; kt < LL / 64; kt++) {
        __syncthreads();  // protect Ks/Vs from previous iteration (and Qs load on iter 0)
        int k0 = kt * 64;
        for (int i = tid; i < 64 * 16; i += 256) {
            int r = i >> 4;
            int c4 = (i & 15) * 4;
            size_t base = ((size_t)((k0 + r) * BBATCH + b)) * 1536;
            float4 kv = *(const float4*)&qkv[base + koff + c4];
            Ks[c4 + 0][r] = kv.x; Ks[c4 + 1][r] = kv.y;
            Ks[c4 + 2][r] = kv.z; Ks[c4 + 3][r] = kv.w;
            float4 vv = *(const float4*)&qkv[base + voff + c4];
            *(float4*)&Vs[r][c4] = vv;
        }
        __syncthreads();

        // S = Q K^T * 1/8
        float s[4][4];
#pragma unroll
        for (int i = 0; i < 4; i++)
#pragma unroll
            for (int j = 0; j < 4; j++) s[i][j] = 0.0f;

        for (int d = 0; d < 64; d++) {
            float4 k4 = *(const float4*)&Ks[d][tx * 4];
            float kv[4] = {k4.x, k4.y, k4.z, k4.w};
#pragma unroll
            for (int i = 0; i < 4; i++) {
                float qv = Qs[ty * 4 + i][d];
#pragma unroll
                for (int j = 0; j < 4; j++)
                    s[i][j] = fmaf(qv, kv[j], s[i][j]);
            }
        }

        // online softmax update (row groups of 16 threads share a row)
#pragma unroll
        for (int i = 0; i < 4; i++) {
#pragma unroll
            for (int j = 0; j < 4; j++) s[i][j] *= 0.125f;
            float mx = fmaxf(fmaxf(s[i][0], s[i][1]), fmaxf(s[i][2], s[i][3]));
#pragma unroll
            for (int off = 1; off < 16; off <<= 1)
                mx = fmaxf(mx, __shfl_xor_sync(0xffffffffu, mx, off));
            float mn = fmaxf(m_i[i], mx);
            float sc = expf(m_i[i] - mn);
            float rs = 0.0f;
#pragma unroll
            for (int j = 0; j < 4; j++) { s[i][j] = expf(s[i][j] - mn); rs += s[i][j]; }
#pragma unroll
            for (int off = 1; off < 16; off <<= 1)
                rs += __shfl_xor_sync(0xffffffffu, rs, off);
            l_i[i] = l_i[i] * sc + rs;
#pragma unroll
            for (int j = 0; j < 4; j++) o[i][j] *= sc;
            m_i[i] = mn;
        }

        __syncthreads();  // all reads of Ks (as K) complete
#pragma unroll
        for (int i = 0; i < 4; i++)
#pragma unroll
            for (int j = 0; j < 4; j++)
                Ps[(ty * 4 + i) * 64 + tx * 4 + j] = s[i][j];
        __syncthreads();

        // O += P V
        for (int m = 0; m < 64; m++) {
            float4 v4 = *(const float4*)&Vs[m][tx * 4];
            float vv[4] = {v4.x, v4.y, v4.z, v4.w};
#pragma unroll
            for (int i = 0; i < 4; i++) {
                float pv = Ps[(ty * 4 + i) * 64 + m];
#pragma unroll
                for (int j = 0; j < 4; j++)
                    o[i][j] = fmaf(pv, vv[j], o[i][j]);
            }
        }
    }

    // write O / l
#pragma unroll
    for (int i = 0; i < 4; i++) {
        float inv = 1.0f / l_i[i];
        float4 o4 = {o[i][0] * inv, o[i][1] * inv, o[i][2] * inv, o[i][3] * inv};
        size_t t = (size_t)((q0 + ty * 4 + i) * BBATCH + b);
        *(float4*)&out[t * EE + h * 64 + tx * 4] = o4;
    }
}

// ---------------- kernel 4: residual add + layernorm ----------------
// one block per token, 256 threads, E=512 (2 elems/thread), two-pass mean/var
__global__ void __launch_bounds__(256)
add_ln_kernel(const float* __restrict__ a, const float* __restrict__ r,
              const float* __restrict__ g, const float* __restrict__ beta,
              float* __restrict__ out) {
    __shared__ float red[8];
    int t = blockIdx.x;
    int tid = threadIdx.x;
    const float* pa = a + (size_t)t * EE;
    const float* pr = r + (size_t)t * EE;
    float v0 = pa[tid] + pr[tid];
    float v1 = pa[tid + 256] + pr[tid + 256];

    float sum = v0 + v1;
#pragma unroll
    for (int off = 16; off > 0; off >>= 1)
        sum += __shfl_xor_sync(0xffffffffu, sum, off);
    if ((tid & 31) == 0) red[tid >> 5] = sum;
    __syncthreads();
    float tot = 0.0f;
#pragma unroll
    for (int w = 0; w < 8; w++) tot += red[w];
    float mu = tot * (1.0f / 512.0f);
    __syncthreads();

    float d0 = v0 - mu, d1 = v1 - mu;
    float sq = d0 * d0 + d1 * d1;
#pragma unroll
    for (int off = 16; off > 0; off >>= 1)
        sq += __shfl_xor_sync(0xffffffffu, sq, off);
    if ((tid & 31) == 0) red[tid >> 5] = sq;
    __syncthreads();
    float vt = 0.0f;
#pragma unroll
    for (int w = 0; w < 8; w++) vt += red[w];
    float var = vt * (1.0f / 512.0f);
    float rstd = rsqrtf(var + 1e-5f);

    out[(size_t)t * EE + tid]       = d0 * rstd * g[tid]       + beta[tid];
    out[(size_t)t * EE + tid + 256] = d1 * rstd * g[tid + 256] + beta[tid + 256];
}

// ---------------- launch ----------------
extern "C" void kernel_launch(void* const* d_in, const int* in_sizes, int n_in,
                              void* d_out, int out_size) {
    const float* x     = (const float*)d_in[0];
    const float* in_w  = (const float*)d_in[1];
    const float* in_b  = (const float*)d_in[2];
    const float* out_w = (const float*)d_in[3];
    const float* out_b = (const float*)d_in[4];
    const float* w1    = (const float*)d_in[5];
    const float* b1    = (const float*)d_in[6];
    const float* w2    = (const float*)d_in[7];
    const float* b2    = (const float*)d_in[8];
    const float* ln_g  = (const float*)d_in[9];
    const float* ln_b  = (const float*)d_in[10];
    float* out = (float*)d_out;

    float *x0, *qkv, *att, *proj, *x1, *hbuf;
    cudaGetSymbolAddress((void**)&x0,   g_x0);
    cudaGetSymbolAddress((void**)&qkv,  g_qkv);
    cudaGetSymbolAddress((void**)&att,  g_att);
    cudaGetSymbolAddress((void**)&proj, g_proj);
    cudaGetSymbolAddress((void**)&x1,   g_x1);
    cudaGetSymbolAddress((void**)&hbuf, g_h);

    // 1. x0 = x + pe
    pe_add_kernel<<<(TT * EE) / 256, 256>>>(x, x0);
    // 2. qkv = x0 @ in_w^T + in_b
    sgemm_nt<0><<<dim3(1536 / 128, TT / 128), 256>>>(x0, in_w, in_b, qkv, TT, 1536, 512);
    // 3. attention
    flash_attn<<<dim3(LL / 64, BBATCH * HH), 256>>>(qkv, att);
    // 4. proj = att @ out_w^T + out_b
    sgemm_nt<0><<<dim3(512 / 128, TT / 128), 256>>>(att, out_w, out_b, proj, TT, 512, 512);
    // 5. x1 = LN(proj + x0)
    add_ln_kernel<<<TT, 256>>>(proj, x0, ln_g, ln_b, x1);
    // 6. h = gelu(x1 @ w1^T + b1)
    sgemm_nt<1><<<dim3(2048 / 128, TT / 128), 256>>>(x1, w1, b1, hbuf, TT, 2048, 512);
    // 7. ff = h @ w2^T + b2   (reuse att buffer)
    sgemm_nt<0><<<dim3(512 / 128, TT / 128), 256>>>(hbuf, w2, b2, att, TT, 512, 2048);
    // 8. out = LN(ff + x1)
    add_ln_kernel<<<TT, 256>>>(att, x1, ln_g, ln_b, out);
}

// round 4
// speedup vs baseline: 2.5477x; 2.5477x over previous
#include <cuda_runtime.h>
#include <math.h>
#include <stdint.h>

#define LL 2048
#define BB 4
#define EE 512
#define HH 8
#define TT (LL*BB)

__device__ float g_x0[TT*EE];
__device__ float g_qkv[TT*3*EE];
__device__ float g_att[TT*EE];
__device__ float g_proj[TT*EE];
__device__ float g_x1[TT*EE];
__device__ float g_h[TT*2048];

__device__ __forceinline__ float f2tf(float x) {
    unsigned u; asm("cvt.rna.tf32.f32 %0, %1;" : "=r"(u) : "f"(x));
    return __uint_as_float(u);
}
__device__ __forceinline__ float gelu_exact(float v) {
    return 0.5f * v * (1.0f + erff(v * 0.70710678118654752f));
}
#define MMA8(c, a, b) asm volatile( \
    "mma.sync.aligned.m16n8k8.row.col.f32.tf32.tf32.f32 " \
    "{%0,%1,%2,%3}, {%4,%5,%6,%7}, {%8,%9}, {%0,%1,%2,%3};\n" \
    : "+f"((c)[0]), "+f"((c)[1]), "+f"((c)[2]), "+f"((c)[3]) \
    : "r"((a)[0]), "r"((a)[1]), "r"((a)[2]), "r"((a)[3]), \
      "r"((b)[0]), "r"((b)[1]))

// ---------------- PE add ----------------
__global__ void pe_add_kernel(const float* __restrict__ x, float* __restrict__ out) {
    int i = blockIdx.x * blockDim.x + threadIdx.x;
    if (i >= TT*EE) return;
    int e = i & (EE - 1);
    int b = (i / EE) & (BB - 1);
    float ef = (e & 1) ? (float)(e + 1) : (float)e;
    float freq = expf(-ef * (9.210340371976184f / 512.0f));
    float arg = (float)(b + 1) * freq;
    float pe = (e & 1) ? cosf(arg) : sinf(arg);
    out[i] = x[i] + pe;
}

// ---------------- tf32 GEMM: C = A[M,K] W[N,K]^T + bias (+GELU) ----------------
// block 128x128, BK=16, 256 thr = 8 warps (2m x 4n), warp 64x32.
// smem row stride 20 floats (=4 mod 32): conflict-free LDS.32 frag loads.
template<int GELU>
__global__ void __launch_bounds__(256)
gemm_tf32(const float* __restrict__ A, const float* __restrict__ W,
          const float* __restrict__ bias, float* __restrict__ C, int N, int K) {
    __shared__ float As[2][128][20];
    __shared__ float Bs[2][128][20];
    const int tid = threadIdx.x, lane = tid & 31, warp = tid >> 5;
    const int g = lane >> 2, t = lane & 3;
    const int wm = warp >> 2, wn = warp & 3;
    const int bRow = blockIdx.y * 128, bCol = blockIdx.x * 128;
    const int lr = tid >> 1, lk = (tid & 1) * 8;

    const float* Ap = A + (size_t)(bRow + lr) * K + lk;
    const float* Wp = W + (size_t)(bCol + lr) * K + lk;

    float c[4][4][4];
#pragma unroll
    for (int ma = 0; ma < 4; ma++)
#pragma unroll
        for (int na = 0; na < 4; na++)
#pragma unroll
            for (int q = 0; q < 4; q++) c[ma][na][q] = 0.0f;

    float4 ra0, ra1, rb0, rb1;
    ra0 = *(const float4*)(Ap);  ra1 = *(const float4*)(Ap + 4);
    rb0 = *(const float4*)(Wp);  rb1 = *(const float4*)(Wp + 4);

    auto sts = [&](int s) {
        float4 v;
        v.x=f2tf(ra0.x); v.y=f2tf(ra0.y); v.z=f2tf(ra0.z); v.w=f2tf(ra0.w);
        *(float4*)&As[s][lr][lk] = v;
        v.x=f2tf(ra1.x); v.y=f2tf(ra1.y); v.z=f2tf(ra1.z); v.w=f2tf(ra1.w);
        *(float4*)&As[s][lr][lk+4] = v;
        v.x=f2tf(rb0.x); v.y=f2tf(rb0.y); v.z=f2tf(rb0.z); v.w=f2tf(rb0.w);
        *(float4*)&Bs[s][lr][lk] = v;
        v.x=f2tf(rb1.x); v.y=f2tf(rb1.y); v.z=f2tf(rb1.z); v.w=f2tf(rb1.w);
        *(float4*)&Bs[s][lr][lk+4] = v;
    };
    sts(0);
    __syncthreads();

    const int KT = K >> 4;
    for (int kt = 0; kt < KT; kt++) {
        const int cur = kt & 1;
        const bool more = (kt + 1 < KT);
        if (more) {
            ra0 = *(const float4*)(Ap + (kt+1)*16);
            ra1 = *(const float4*)(Ap + (kt+1)*16 + 4);
            rb0 = *(const float4*)(Wp + (kt+1)*16);
            rb1 = *(const float4*)(Wp + (kt+1)*16 + 4);
        }
#pragma unroll
        for (int kb = 0; kb < 2; kb++) {
            unsigned a[4][4], bf[4][2];
#pragma unroll
            for (int ma = 0; ma < 4; ma++) {
                int r = wm*64 + ma*16 + g;
                a[ma][0] = __float_as_uint(As[cur][r][kb*8+t]);
                a[ma][1] = __float_as_uint(As[cur][r+8][kb*8+t]);
                a[ma][2] = __float_as_uint(As[cur][r][kb*8+t+4]);
                a[ma][3] = __float_as_uint(As[cur][r+8][kb*8+t+4]);
            }
#pragma unroll
            for (int na = 0; na < 4; na++) {
                int cc = wn*32 + na*8 + g;
                bf[na][0] = __float_as_uint(Bs[cur][cc][kb*8+t]);
                bf[na][1] = __float_as_uint(Bs[cur][cc][kb*8+t+4]);
            }
#pragma unroll
            for (int ma = 0; ma < 4; ma++)
#pragma unroll
                for (int na = 0; na < 4; na++)
                    MMA8(c[ma][na], a[ma], bf[na]);
        }
        if (more) sts(cur ^ 1);
        __syncthreads();
    }

#pragma unroll
    for (int ma = 0; ma < 4; ma++) {
#pragma unroll
        for (int na = 0; na < 4; na++) {
            int col = bCol + wn*32 + na*8 + 2*t;
            int row = bRow + wm*64 + ma*16 + g;
            float b0 = bias[col], b1 = bias[col+1];
            float v0 = c[ma][na][0]+b0, v1 = c[ma][na][1]+b1;
            float v2 = c[ma][na][2]+b0, v3 = c[ma][na][3]+b1;
            if (GELU) { v0=gelu_exact(v0); v1=gelu_exact(v1);
                        v2=gelu_exact(v2); v3=gelu_exact(v3); }
            float2 p0 = {v0,v1}, p1 = {v2,v3};
            *(float2*)&C[(size_t)row*N + col] = p0;
            *(float2*)&C[(size_t)(row+8)*N + col] = p1;
        }
    }
}

// ---------------- tf32 flash attention ----------------
// grid (L/64, B*H), 128 threads = 4 warps, warp = 16 q-rows.
// Qs/Ks/Vs [64][68] dynamic smem; Ps reuses Ks.
__global__ void __launch_bounds__(128)
attn_tf32(const float* __restrict__ qkv, float* __restrict__ out) {
    extern __shared__ float sm[];
    float (*Qs)[68] = (float(*)[68])sm;
    float (*Ks)[68] = (float(*)[68])(sm + 64*68);
    float (*Vs)[68] = (float(*)[68])(sm + 2*64*68);
    float (*Ps)[68] = Ks;

    const int tid = threadIdx.x, lane = tid & 31, warp = tid >> 5;
    const int g = lane >> 2, t = lane & 3;
    const int q0 = blockIdx.x * 64;
    const int b = blockIdx.y >> 3, h = blockIdx.y & 7;
    const int w16 = warp * 16;
    const size_t qoff = h*64, koff = 512 + h*64, voff = 1024 + h*64;

    for (int i = tid; i < 64*16; i += 128) {
        int r = i >> 4, c4 = (i & 15) * 4;
        float4 v = *(const float4*)&qkv[((size_t)((q0+r)*BB + b))*1536 + qoff + c4];
        float4 cv = {f2tf(v.x), f2tf(v.y), f2tf(v.z), f2tf(v.w)};
        *(float4*)&Qs[r][c4] = cv;
    }

    float m_[2] = {-1e30f, -1e30f}, l_[2] = {0.0f, 0.0f};
    float o[8][4];
#pragma unroll
    for (int nf = 0; nf < 8; nf++)
#pragma unroll
        for (int q = 0; q < 4; q++) o[nf][q] = 0.0f;

    for (int kt = 0; kt < LL/64; kt++) {
        __syncthreads();
        int k0 = kt * 64;
        for (int i = tid; i < 64*16; i += 128) {
            int r = i >> 4, c4 = (i & 15) * 4;
            size_t base = ((size_t)((k0+r)*BB + b))*1536;
            float4 kv = *(const float4*)&qkv[base + koff + c4];
            float4 ck = {f2tf(kv.x), f2tf(kv.y), f2tf(kv.z), f2tf(kv.w)};
            *(float4*)&Ks[r][c4] = ck;
            float4 vv = *(const float4*)&qkv[base + voff + c4];
            float4 cv = {f2tf(vv.x), f2tf(vv.y), f2tf(vv.z), f2tf(vv.w)};
            *(float4*)&Vs[r][c4] = cv;
        }
        __syncthreads();

        float s[8][4];
#pragma unroll
        for (int nf = 0; nf < 8; nf++)
#pragma unroll
            for (int q = 0; q < 4; q++) s[nf][q] = 0.0f;

#pragma unroll
        for (int kb = 0; kb < 8; kb++) {
            unsigned a[4], bf[8][2];
            a[0] = __float_as_uint(Qs[w16+g][kb*8+t]);
            a[1] = __float_as_uint(Qs[w16+g+8][kb*8+t]);
            a[2] = __float_as_uint(Qs[w16+g][kb*8+t+4]);
            a[3] = __float_as_uint(Qs[w16+g+8][kb*8+t+4]);
#pragma unroll
            for (int nf = 0; nf < 8; nf++) {
                bf[nf][0] = __float_as_uint(Ks[nf*8+g][kb*8+t]);
                bf[nf][1] = __float_as_uint(Ks[nf*8+g][kb*8+t+4]);
            }
#pragma unroll
            for (int nf = 0; nf < 8; nf++) MMA8(s[nf], a, bf[nf]);
        }

        // online softmax per row-half (rows g and g+8 of warp strip)
#pragma unroll
        for (int hf = 0; hf < 2; hf++) {
            float mx = -1e30f;
#pragma unroll
            for (int nf = 0; nf < 8; nf++) {
                s[nf][2*hf]   *= 0.125f;
                s[nf][2*hf+1] *= 0.125f;
                mx = fmaxf(mx, fmaxf(s[nf][2*hf], s[nf][2*hf+1]));
            }
            mx = fmaxf(mx, __shfl_xor_sync(0xffffffffu, mx, 1));
            mx = fmaxf(mx, __shfl_xor_sync(0xffffffffu, mx, 2));
            float mn = fmaxf(m_[hf], mx);
            float sc = __expf(m_[hf] - mn);
            float rs = 0.0f;
#pragma unroll
            for (int nf = 0; nf < 8; nf++) {
                s[nf][2*hf]   = __expf(s[nf][2*hf]   - mn);
                s[nf][2*hf+1] = __expf(s[nf][2*hf+1] - mn);
                rs += s[nf][2*hf] + s[nf][2*hf+1];
            }
            rs += __shfl_xor_sync(0xffffffffu, rs, 1);
            rs += __shfl_xor_sync(0xffffffffu, rs, 2);
            l_[hf] = l_[hf] * sc + rs;
#pragma unroll
            for (int nf = 0; nf < 8; nf++) {
                o[nf][2*hf] *= sc; o[nf][2*hf+1] *= sc;
            }
            m_[hf] = mn;
        }

        __syncthreads();   // all warps done reading Ks
#pragma unroll
        for (int nf = 0; nf < 8; nf++) {
            float2 p0 = {f2tf(s[nf][0]), f2tf(s[nf][1])};
            float2 p1 = {f2tf(s[nf][2]), f2tf(s[nf][3])};
            *(float2*)&Ps[w16+g][nf*8+2*t]   = p0;
            *(float2*)&Ps[w16+g+8][nf*8+2*t] = p1;
        }
        __syncthreads();

#pragma unroll
        for (int kb = 0; kb < 8; kb++) {
            unsigned a[4], bf[8][2];
            a[0] = __float_as_uint(Ps[w16+g][kb*8+t]);
            a[1] = __float_as_uint(Ps[w16+g+8][kb*8+t]);
            a[2] = __float_as_uint(Ps[w16+g][kb*8+t+4]);
            a[3] = __float_as_uint(Ps[w16+g+8][kb*8+t+4]);
#pragma unroll
            for (int nf = 0; nf < 8; nf++) {
                bf[nf][0] = __float_as_uint(Vs[kb*8+t][nf*8+g]);
                bf[nf][1] = __float_as_uint(Vs[kb*8+t+4][nf*8+g]);
            }
#pragma unroll
            for (int nf = 0; nf < 8; nf++) MMA8(o[nf], a, bf[nf]);
        }
    }

#pragma unroll
    for (int hf = 0; hf < 2; hf++) {
        float inv = 1.0f / l_[hf];
        int row = q0 + w16 + g + 8*hf;
        size_t base = ((size_t)row*BB + b)*512 + h*64;
#pragma unroll
        for (int nf = 0; nf < 8; nf++) {
            float2 p = {o[nf][2*hf]*inv, o[nf][2*hf+1]*inv};
            *(float2*)&out[base + nf*8 + 2*t] = p;
        }
    }
}

// ---------------- residual add + layernorm ----------------
__global__ void __launch_bounds__(256)
add_ln_kernel(const float* __restrict__ a, const float* __restrict__ r,
              const float* __restrict__ g, const float* __restrict__ beta,
              float* __restrict__ out) {
    __shared__ float red[8];
    int t = blockIdx.x;
    int tid = threadIdx.x;
    const float* pa = a + (size_t)t * EE;
    const float* pr = r + (size_t)t * EE;
    float v0 = pa[tid] + pr[tid];
    float v1 = pa[tid + 256] + pr[tid + 256];
    float sum = v0 + v1;
#pragma unroll
    for (int off = 16; off > 0; off >>= 1)
        sum += __shfl_xor_sync(0xffffffffu, sum, off);
    if ((tid & 31) == 0) red[tid >> 5] = sum;
    __syncthreads();
    float tot = 0.0f;
#pragma unroll
    for (int w = 0; w < 8; w++) tot += red[w];
    float mu = tot * (1.0f / 512.0f);
    __syncthreads();
    float d0 = v0 - mu, d1 = v1 - mu;
    float sq = d0*d0 + d1*d1;
#pragma unroll
    for (int off = 16; off > 0; off >>= 1)
        sq += __shfl_xor_sync(0xffffffffu, sq, off);
    if ((tid & 31) == 0) red[tid >> 5] = sq;
    __syncthreads();
    float vt = 0.0f;
#pragma unroll
    for (int w = 0; w < 8; w++) vt += red[w];
    float rstd = rsqrtf(vt * (1.0f / 512.0f) + 1e-5f);
    out[(size_t)t*EE + tid]       = d0 * rstd * g[tid]       + beta[tid];
    out[(size_t)t*EE + tid + 256] = d1 * rstd * g[tid + 256] + beta[tid + 256];
}

// ---------------- launch ----------------
extern "C" void kernel_launch(void* const* d_in, const int* in_sizes, int n_in,
                              void* d_out, int out_size) {
    const float* x     = (const float*)d_in[0];
    const float* in_w  = (const float*)d_in[1];
    const float* in_b  = (const float*)d_in[2];
    const float* out_w = (const float*)d_in[3];
    const float* out_b = (const float*)d_in[4];
    const float* w1    = (const float*)d_in[5];
    const float* b1    = (const float*)d_in[6];
    const float* w2    = (const float*)d_in[7];
    const float* b2    = (const float*)d_in[8];
    const float* ln_g  = (const float*)d_in[9];
    const float* ln_b  = (const float*)d_in[10];
    float* out = (float*)d_out;

    float *x0, *qkv, *att, *proj, *x1, *hbuf;
    cudaGetSymbolAddress((void**)&x0,   g_x0);
    cudaGetSymbolAddress((void**)&qkv,  g_qkv);
    cudaGetSymbolAddress((void**)&att,  g_att);
    cudaGetSymbolAddress((void**)&proj, g_proj);
    cudaGetSymbolAddress((void**)&x1,   g_x1);
    cudaGetSymbolAddress((void**)&hbuf, g_h);

    const int attn_smem = 3 * 64 * 68 * sizeof(float);
    cudaFuncSetAttribute(attn_tf32, cudaFuncAttributeMaxDynamicSharedMemorySize, attn_smem);

    pe_add_kernel<<<(TT*EE)/256, 256>>>(x, x0);
    gemm_tf32<0><<<dim3(1536/128, TT/128), 256>>>(x0, in_w, in_b, qkv, 1536, 512);
    attn_tf32<<<dim3(LL/64, BB*HH), 128, attn_smem>>>(qkv, att);
    gemm_tf32<0><<<dim3(512/128, TT/128), 256>>>(att, out_w, out_b, proj, 512, 512);
    add_ln_kernel<<<TT, 256>>>(proj, x0, ln_g, ln_b, x1);
    gemm_tf32<1><<<dim3(2048/128, TT/128), 256>>>(x1, w1, b1, hbuf, 2048, 512);
    gemm_tf32<0><<<dim3(512/128, TT/128), 256>>>(hbuf, w2, b2, att, 512, 2048);
    add_ln_kernel<<<TT, 256>>>(att, x1, ln_g, ln_b, out);
}

// round 6
// speedup vs baseline: 2.6024x; 1.0215x over previous
#include <cuda_runtime.h>
#include <math.h>
#include <stdint.h>

#define LL 2048
#define BB 4
#define EE 512
#define HH 8
#define TT (LL*BB)

__device__ float g_x0[TT*EE];
__device__ float g_qkv[TT*3*EE];
__device__ float g_att[TT*EE];
__device__ float g_proj[TT*EE];
__device__ float g_x1[TT*EE];
__device__ float g_h[TT*2048];

__device__ __forceinline__ float f2tf(float x) {
    unsigned u; asm("cvt.rna.tf32.f32 %0, %1;" : "=r"(u) : "f"(x));
    return __uint_as_float(u);
}
__device__ __forceinline__ unsigned f2tfu(float x) {
    unsigned u; asm("cvt.rna.tf32.f32 %0, %1;" : "=r"(u) : "f"(x));
    return u;
}
__device__ __forceinline__ float gelu_exact(float v) {
    return 0.5f * v * (1.0f + erff(v * 0.70710678118654752f));
}
__device__ __forceinline__ void cp16(void* smem_dst, const void* gsrc) {
    unsigned s = (unsigned)__cvta_generic_to_shared(smem_dst);
    asm volatile("cp.async.cg.shared.global [%0], [%1], 16;" :: "r"(s), "l"(gsrc));
}
#define CP_COMMIT() asm volatile("cp.async.commit_group;")
#define CP_WAIT1()  asm volatile("cp.async.wait_group 1;")

#define MMA8(c, a, b) asm volatile( \
    "mma.sync.aligned.m16n8k8.row.col.f32.tf32.tf32.f32 " \
    "{%0,%1,%2,%3}, {%4,%5,%6,%7}, {%8,%9}, {%0,%1,%2,%3};\n" \
    : "+f"((c)[0]), "+f"((c)[1]), "+f"((c)[2]), "+f"((c)[3]) \
    : "r"((a)[0]), "r"((a)[1]), "r"((a)[2]), "r"((a)[3]), \
      "r"((b)[0]), "r"((b)[1]))

// ---------------- PE add ----------------
__global__ void pe_add_kernel(const float* __restrict__ x, float* __restrict__ out) {
    int i = blockIdx.x * blockDim.x + threadIdx.x;
    if (i >= TT*EE) return;
    int e = i & (EE - 1);
    int b = (i / EE) & (BB - 1);
    float ef = (e & 1) ? (float)(e + 1) : (float)e;
    float freq = expf(-ef * (9.210340371976184f / 512.0f));
    float arg = (float)(b + 1) * freq;
    float pe = (e & 1) ? cosf(arg) : sinf(arg);
    out[i] = x[i] + pe;
}

// ---------------- tf32 GEMM, 3-stage cp.async -----------------
// C[M,N] = A[M,K] W[N,K]^T + bias (+GELU). block 128x128, BK=16,
// 256 thr = 8 warps (2m x 4n), warp 64x32. smem row stride 20 floats.
// fp32 raw in smem; cvt to tf32 at fragment-load time.
#define GSTRIDE 20
#define GSTAGE  (128*GSTRIDE)

template<int GELU>
__global__ void __launch_bounds__(256)
gemm_tf32(const float* __restrict__ A, const float* __restrict__ W,
          const float* __restrict__ bias, float* __restrict__ C, int N, int K) {
    extern __shared__ float sm[];
    float* As_ = sm;                 // [3][128][20]
    float* Bs_ = sm + 3*GSTAGE;      // [3][128][20]

    const int tid = threadIdx.x, lane = tid & 31, warp = tid >> 5;
    const int g = lane >> 2, t = lane & 3;
    const int wm = warp >> 2, wn = warp & 3;
    const int bRow = blockIdx.y * 128, bCol = blockIdx.x * 128;
    const int lr = tid >> 1, lk = (tid & 1) * 8;

    const float* Ap = A + (size_t)(bRow + lr) * K + lk;
    const float* Wp = W + (size_t)(bCol + lr) * K + lk;

    float c[4][4][4];
#pragma unroll
    for (int ma = 0; ma < 4; ma++)
#pragma unroll
        for (int na = 0; na < 4; na++)
#pragma unroll
            for (int q = 0; q < 4; q++) c[ma][na][q] = 0.0f;

    const int KT = K >> 4;

    auto issue = [&](int s, int kt) {
        float* as = As_ + s*GSTAGE + lr*GSTRIDE + lk;
        float* bs = Bs_ + s*GSTAGE + lr*GSTRIDE + lk;
        cp16(as,     Ap + kt*16);
        cp16(as + 4, Ap + kt*16 + 4);
        cp16(bs,     Wp + kt*16);
        cp16(bs + 4, Wp + kt*16 + 4);
    };

    issue(0, 0); CP_COMMIT();
    issue(1, 1); CP_COMMIT();
    CP_WAIT1();
    __syncthreads();

    for (int kt = 0; kt < KT; kt++) {
        const int cur = kt % 3;
        const float* As = As_ + cur*GSTAGE;
        const float* Bs = Bs_ + cur*GSTAGE;

#pragma unroll
        for (int kb = 0; kb < 2; kb++) {
            unsigned a[4][4], bf[4][2];
#pragma unroll
            for (int ma = 0; ma < 4; ma++) {
                int r = wm*64 + ma*16 + g;
                a[ma][0] = f2tfu(As[r*GSTRIDE + kb*8 + t]);
                a[ma][1] = f2tfu(As[(r+8)*GSTRIDE + kb*8 + t]);
                a[ma][2] = f2tfu(As[r*GSTRIDE + kb*8 + t + 4]);
                a[ma][3] = f2tfu(As[(r+8)*GSTRIDE + kb*8 + t + 4]);
            }
#pragma unroll
            for (int na = 0; na < 4; na++) {
                int cc = wn*32 + na*8 + g;
                bf[na][0] = f2tfu(Bs[cc*GSTRIDE + kb*8 + t]);
                bf[na][1] = f2tfu(Bs[cc*GSTRIDE + kb*8 + t + 4]);
            }
#pragma unroll
            for (int ma = 0; ma < 4; ma++)
#pragma unroll
                for (int na = 0; na < 4; na++)
                    MMA8(c[ma][na], a[ma], bf[na]);
        }

        if (kt + 2 < KT) issue((kt + 2) % 3, kt + 2);
        CP_COMMIT();
        CP_WAIT1();
        __syncthreads();
    }

#pragma unroll
    for (int ma = 0; ma < 4; ma++) {
#pragma unroll
        for (int na = 0; na < 4; na++) {
            int col = bCol + wn*32 + na*8 + 2*t;
            int row = bRow + wm*64 + ma*16 + g;
            float b0 = bias[col], b1 = bias[col+1];
            float v0 = c[ma][na][0]+b0, v1 = c[ma][na][1]+b1;
            float v2 = c[ma][na][2]+b0, v3 = c[ma][na][3]+b1;
            if (GELU) { v0=gelu_exact(v0); v1=gelu_exact(v1);
                        v2=gelu_exact(v2); v3=gelu_exact(v3); }
            float2 p0 = {v0,v1}, p1 = {v2,v3};
            *(float2*)&C[(size_t)row*N + col] = p0;
            *(float2*)&C[(size_t)(row+8)*N + col] = p1;
        }
    }
}

// ---------------- tf32 flash attention, Q-tile 128 ----------------
// grid (L/128, B*H), 256 threads = 8 warps, warp = 16 q-rows.
// smem: Qs[128][68], Ps[128][68], Ks[64][68], Vs[64][68] (tf32-converted)
__global__ void __launch_bounds__(256)
attn_tf32(const float* __restrict__ qkv, float* __restrict__ out) {
    extern __shared__ float sm[];
    float (*Qs)[68] = (float(*)[68])sm;
    float (*Ps)[68] = (float(*)[68])(sm + 128*68);
    float (*Ks)[68] = (float(*)[68])(sm + 2*128*68);
    float (*Vs)[68] = (float(*)[68])(sm + 2*128*68 + 64*68);

    const int tid = threadIdx.x, lane = tid & 31, warp = tid >> 5;
    const int g = lane >> 2, t = lane & 3;
    const int q0 = blockIdx.x * 128;
    const int b = blockIdx.y >> 3, h = blockIdx.y & 7;
    const int w16 = warp * 16;
    const size_t qoff = h*64, koff = 512 + h*64, voff = 1024 + h*64;

    for (int i = tid; i < 128*16; i += 256) {
        int r = i >> 4, c4 = (i & 15) * 4;
        float4 v = *(const float4*)&qkv[((size_t)((q0+r)*BB + b))*1536 + qoff + c4];
        float4 cv = {f2tf(v.x), f2tf(v.y), f2tf(v.z), f2tf(v.w)};
        *(float4*)&Qs[r][c4] = cv;
    }

    float m_[2] = {-1e30f, -1e30f}, l_[2] = {0.0f, 0.0f};
    float o[8][4];
#pragma unroll
    for (int nf = 0; nf < 8; nf++)
#pragma unroll
        for (int q = 0; q < 4; q++) o[nf][q] = 0.0f;

    for (int kt = 0; kt < LL/64; kt++) {
        __syncthreads();  // Ks/Vs free (also covers Qs on iter 0)
        int k0 = kt * 64;
        for (int i = tid; i < 64*16; i += 256) {
            int r = i >> 4, c4 = (i & 15) * 4;
            size_t base = ((size_t)((k0+r)*BB + b))*1536;
            float4 kv = *(const float4*)&qkv[base + koff + c4];
            float4 ck = {f2tf(kv.x), f2tf(kv.y), f2tf(kv.z), f2tf(kv.w)};
            *(float4*)&Ks[r][c4] = ck;
            float4 vv = *(const float4*)&qkv[base + voff + c4];
            float4 cv = {f2tf(vv.x), f2tf(vv.y), f2tf(vv.z), f2tf(vv.w)};
            *(float4*)&Vs[r][c4] = cv;
        }
        __syncthreads();

        float s[8][4];
#pragma unroll
        for (int nf = 0; nf < 8; nf++)
#pragma unroll
            for (int q = 0; q < 4; q++) s[nf][q] = 0.0f;

#pragma unroll
        for (int kb = 0; kb < 8; kb++) {
            unsigned a[4], bf[8][2];
            a[0] = __float_as_uint(Qs[w16+g][kb*8+t]);
            a[1] = __float_as_uint(Qs[w16+g+8][kb*8+t]);
            a[2] = __float_as_uint(Qs[w16+g][kb*8+t+4]);
            a[3] = __float_as_uint(Qs[w16+g+8][kb*8+t+4]);
#pragma unroll
            for (int nf = 0; nf < 8; nf++) {
                bf[nf][0] = __float_as_uint(Ks[nf*8+g][kb*8+t]);
                bf[nf][1] = __float_as_uint(Ks[nf*8+g][kb*8+t+4]);
            }
#pragma unroll
            for (int nf = 0; nf < 8; nf++) MMA8(s[nf], a, bf[nf]);
        }

#pragma unroll
        for (int hf = 0; hf < 2; hf++) {
            float mx = -1e30f;
#pragma unroll
            for (int nf = 0; nf < 8; nf++) {
                s[nf][2*hf]   *= 0.125f;
                s[nf][2*hf+1] *= 0.125f;
                mx = fmaxf(mx, fmaxf(s[nf][2*hf], s[nf][2*hf+1]));
            }
            mx = fmaxf(mx, __shfl_xor_sync(0xffffffffu, mx, 1));
            mx = fmaxf(mx, __shfl_xor_sync(0xffffffffu, mx, 2));
            float mn = fmaxf(m_[hf], mx);
            float sc = __expf(m_[hf] - mn);
            float rs = 0.0f;
#pragma unroll
            for (int nf = 0; nf < 8; nf++) {
                s[nf][2*hf]   = __expf(s[nf][2*hf]   - mn);
                s[nf][2*hf+1] = __expf(s[nf][2*hf+1] - mn);
                rs += s[nf][2*hf] + s[nf][2*hf+1];
            }
            rs += __shfl_xor_sync(0xffffffffu, rs, 1);
            rs += __shfl_xor_sync(0xffffffffu, rs, 2);
            l_[hf] = l_[hf] * sc + rs;
#pragma unroll
            for (int nf = 0; nf < 8; nf++) {
                o[nf][2*hf] *= sc; o[nf][2*hf+1] *= sc;
            }
            m_[hf] = mn;
        }

        // P rows are warp-private: only a warp-level barrier needed
#pragma unroll
        for (int nf = 0; nf < 8; nf++) {
            float2 p0 = {f2tf(s[nf][0]), f2tf(s[nf][1])};
            float2 p1 = {f2tf(s[nf][2]), f2tf(s[nf][3])};
            *(float2*)&Ps[w16+g][nf*8+2*t]   = p0;
            *(float2*)&Ps[w16+g+8][nf*8+2*t] = p1;
        }
        __syncwarp();

#pragma unroll
        for (int kb = 0; kb < 8; kb++) {
            unsigned a[4], bf[8][2];
            a[0] = __float_as_uint(Ps[w16+g][kb*8+t]);
            a[1] = __float_as_uint(Ps[w16+g+8][kb*8+t]);
            a[2] = __float_as_uint(Ps[w16+g][kb*8+t+4]);
            a[3] = __float_as_uint(Ps[w16+g+8][kb*8+t+4]);
#pragma unroll
            for (int nf = 0; nf < 8; nf++) {
                bf[nf][0] = __float_as_uint(Vs[kb*8+t][nf*8+g]);
                bf[nf][1] = __float_as_uint(Vs[kb*8+t+4][nf*8+g]);
            }
#pragma unroll
            for (int nf = 0; nf < 8; nf++) MMA8(o[nf], a, bf[nf]);
        }
    }

#pragma unroll
    for (int hf = 0; hf < 2; hf++) {
        float inv = 1.0f / l_[hf];
        int row = q0 + w16 + g + 8*hf;
        size_t base = ((size_t)row*BB + b)*512 + h*64;
#pragma unroll
        for (int nf = 0; nf < 8; nf++) {
            float2 p = {o[nf][2*hf]*inv, o[nf][2*hf+1]*inv};
            *(float2*)&out[base + nf*8 + 2*t] = p;
        }
    }
}

// ---------------- residual add + layernorm ----------------
__global__ void __launch_bounds__(256)
add_ln_kernel(const float* __restrict__ a, const float* __restrict__ r,
              const float* __restrict__ g, const float* __restrict__ beta,
              float* __restrict__ out) {
    __shared__ float red[8];
    int t = blockIdx.x;
    int tid = threadIdx.x;
    const float* pa = a + (size_t)t * EE;
    const float* pr = r + (size_t)t * EE;
    float v0 = pa[tid] + pr[tid];
    float v1 = pa[tid + 256] + pr[tid + 256];
    float sum = v0 + v1;
#pragma unroll
    for (int off = 16; off > 0; off >>= 1)
        sum += __shfl_xor_sync(0xffffffffu, sum, off);
    if ((tid & 31) == 0) red[tid >> 5] = sum;
    __syncthreads();
    float tot = 0.0f;
#pragma unroll
    for (int w = 0; w < 8; w++) tot += red[w];
    float mu = tot * (1.0f / 512.0f);
    __syncthreads();
    float d0 = v0 - mu, d1 = v1 - mu;
    float sq = d0*d0 + d1*d1;
#pragma unroll
    for (int off = 16; off > 0; off >>= 1)
        sq += __shfl_xor_sync(0xffffffffu, sq, off);
    if ((tid & 31) == 0) red[tid >> 5] = sq;
    __syncthreads();
    float vt = 0.0f;
#pragma unroll
    for (int w = 0; w < 8; w++) vt += red[w];
    float rstd = rsqrtf(vt * (1.0f / 512.0f) + 1e-5f);
    out[(size_t)t*EE + tid]       = d0 * rstd * g[tid]       + beta[tid];
    out[(size_t)t*EE + tid + 256] = d1 * rstd * g[tid + 256] + beta[tid + 256];
}

// ---------------- launch ----------------
extern "C" void kernel_launch(void* const* d_in, const int* in_sizes, int n_in,
                              void* d_out, int out_size) {
    const float* x     = (const float*)d_in[0];
    const float* in_w  = (const float*)d_in[1];
    const float* in_b  = (const float*)d_in[2];
    const float* out_w = (const float*)d_in[3];
    const float* out_b = (const float*)d_in[4];
    const float* w1    = (const float*)d_in[5];
    const float* b1    = (const float*)d_in[6];
    const float* w2    = (const float*)d_in[7];
    const float* b2    = (const float*)d_in[8];
    const float* ln_g  = (const float*)d_in[9];
    const float* ln_b  = (const float*)d_in[10];
    float* out = (float*)d_out;

    float *x0, *qkv, *att, *proj, *x1, *hbuf;
    cudaGetSymbolAddress((void**)&x0,   g_x0);
    cudaGetSymbolAddress((void**)&qkv,  g_qkv);
    cudaGetSymbolAddress((void**)&att,  g_att);
    cudaGetSymbolAddress((void**)&proj, g_proj);
    cudaGetSymbolAddress((void**)&x1,   g_x1);
    cudaGetSymbolAddress((void**)&hbuf, g_h);

    const int gemm_smem = 6 * GSTAGE * (int)sizeof(float);       // 61440
    const int attn_smem = (2*128 + 2*64) * 68 * (int)sizeof(float);  // 104448
    cudaFuncSetAttribute(gemm_tf32<0>, cudaFuncAttributeMaxDynamicSharedMemorySize, gemm_smem);
    cudaFuncSetAttribute(gemm_tf32<1>, cudaFuncAttributeMaxDynamicSharedMemorySize, gemm_smem);
    cudaFuncSetAttribute(attn_tf32, cudaFuncAttributeMaxDynamicSharedMemorySize, attn_smem);

    pe_add_kernel<<<(TT*EE)/256, 256>>>(x, x0);
    gemm_tf32<0><<<dim3(1536/128, TT/128), 256, gemm_smem>>>(x0, in_w, in_b, qkv, 1536, 512);
    attn_tf32<<<dim3(LL/128, BB*HH), 256, attn_smem>>>(qkv, att);
    gemm_tf32<0><<<dim3(512/128, TT/128), 256, gemm_smem>>>(att, out_w, out_b, proj, 512, 512);
    add_ln_kernel<<<TT, 256>>>(proj, x0, ln_g, ln_b, x1);
    gemm_tf32<1><<<dim3(2048/128, TT/128), 256, gemm_smem>>>(x1, w1, b1, hbuf, 2048, 512);
    gemm_tf32<0><<<dim3(512/128, TT/128), 256, gemm_smem>>>(hbuf, w2, b2, att, 512, 2048);
    add_ln_kernel<<<TT, 256>>>(att, x1, ln_g, ln_b, out);
}

// round 7
// speedup vs baseline: 5.5606x; 2.1367x over previous
#include <cuda_runtime.h>
#include <cuda_fp16.h>
#include <math.h>
#include <stdint.h>

#define LL 2048
#define BB 4
#define EE 512
#define HH 8
#define TT (LL*BB)

// ---------------- scratch ----------------
__device__ float  g_x0 [TT*EE];      // residual 1 (fp32)
__device__ float  g_proj[TT*EE];     // out-proj result (fp32)
__device__ float  g_x1 [TT*EE];      // after LN1 (fp32 residual)
__device__ float  g_ff [TT*EE];      // ffn2 result (fp32)
__device__ __half g_x0h [TT*EE];
__device__ __half g_qkvh[TT*3*EE];
__device__ __half g_atth[TT*EE];
__device__ __half g_x1h [TT*EE];
__device__ __half g_hh  [TT*2048];
__device__ __half g_wh  [3145728];   // in_w | out_w | w1 | w2 (fp16)
#define WOFF_IN  0
#define WOFF_OUT 786432
#define WOFF_W1  1048576
#define WOFF_W2  2097152

// ---------------- helpers ----------------
__device__ __forceinline__ float gelu_exact(float v) {
    return 0.5f * v * (1.0f + erff(v * 0.70710678118654752f));
}
__device__ __forceinline__ void cp16(void* smem_dst, const void* gsrc) {
    unsigned s = (unsigned)__cvta_generic_to_shared(smem_dst);
    asm volatile("cp.async.cg.shared.global [%0], [%1], 16;" :: "r"(s), "l"(gsrc));
}
#define CP_COMMIT() asm volatile("cp.async.commit_group;")
#define CP_WAIT1()  asm volatile("cp.async.wait_group 1;")

__device__ __forceinline__ uint4 ldsm4(const void* p) {
    unsigned s = (unsigned)__cvta_generic_to_shared(p);
    uint4 v;
    asm volatile("ldmatrix.sync.aligned.m8n8.x4.shared.b16 {%0,%1,%2,%3}, [%4];"
                 : "=r"(v.x), "=r"(v.y), "=r"(v.z), "=r"(v.w) : "r"(s));
    return v;
}
__device__ __forceinline__ uint4 ldsm4t(const void* p) {
    unsigned s = (unsigned)__cvta_generic_to_shared(p);
    uint4 v;
    asm volatile("ldmatrix.sync.aligned.m8n8.x4.trans.shared.b16 {%0,%1,%2,%3}, [%4];"
                 : "=r"(v.x), "=r"(v.y), "=r"(v.z), "=r"(v.w) : "r"(s));
    return v;
}
#define MMA16(c, a0,a1,a2,a3, b0,b1) asm volatile( \
    "mma.sync.aligned.m16n8k16.row.col.f32.f16.f16.f32 " \
    "{%0,%1,%2,%3}, {%4,%5,%6,%7}, {%8,%9}, {%0,%1,%2,%3};\n" \
    : "+f"((c)[0]), "+f"((c)[1]), "+f"((c)[2]), "+f"((c)[3]) \
    : "r"(a0), "r"(a1), "r"(a2), "r"(a3), "r"(b0), "r"(b1))

// ---------------- fp32 -> fp16 convert ----------------
__global__ void f2h_kernel(const float* __restrict__ s, __half* __restrict__ d, int n) {
    int i = blockIdx.x * blockDim.x + threadIdx.x;
    if (i < n) d[i] = __float2half_rn(s[i]);
}

// ---------------- PE add (fp32 + fp16 outputs) ----------------
__global__ void pe_add_kernel(const float* __restrict__ x,
                              float* __restrict__ out, __half* __restrict__ outh) {
    int i = blockIdx.x * blockDim.x + threadIdx.x;
    if (i >= TT*EE) return;
    int e = i & (EE - 1);
    int b = (i / EE) & (BB - 1);
    float ef = (e & 1) ? (float)(e + 1) : (float)e;
    float freq = expf(-ef * (9.210340371976184f / 512.0f));
    float arg = (float)(b + 1) * freq;
    float pe = (e & 1) ? cosf(arg) : sinf(arg);
    float v = x[i] + pe;
    out[i] = v;
    outh[i] = __float2half_rn(v);
}

// ---------------- fp16 GEMM, 3-stage cp.async, ldmatrix -----------------
// C[M,N] = A[M,K] W[N,K]^T + bias (+GELU). block 128x128, BK=32,
// 256 thr = 8 warps (2m x 4n), warp 64x32. smem stride 40 halves (80B, odd*16B).
#define HSTRIDE 40
#define HSTAGE  (128*HSTRIDE)

template<int GELU, int HALF_OUT>
__global__ void __launch_bounds__(256)
gemm_h(const __half* __restrict__ A, const __half* __restrict__ W,
       const float* __restrict__ bias, float* __restrict__ Cf,
       __half* __restrict__ Ch, int N, int K) {
    extern __shared__ __half smh[];
    __half* As_ = smh;               // [3][128][40]
    __half* Bs_ = smh + 3*HSTAGE;    // [3][128][40]

    const int tid = threadIdx.x, lane = tid & 31, warp = tid >> 5;
    const int g = lane >> 2, t = lane & 3;
    const int wm = warp >> 2, wn = warp & 3;
    const int bRow = blockIdx.y * 128, bCol = blockIdx.x * 128;
    const int lr = tid >> 1, ho = (tid & 1) * 16;
    const int l15 = lane & 15, lhi8 = (lane >> 4) << 3;
    const int bn = (lane & 7) + ((lane & 16) >> 1);   // B ldsm row within 16
    const int bk = lane & 8;                          // B ldsm k offset

    const __half* Ap = A + (size_t)(bRow + lr) * K + ho;
    const __half* Wp = W + (size_t)(bCol + lr) * K + ho;

    float c[4][4][4];
#pragma unroll
    for (int ma = 0; ma < 4; ma++)
#pragma unroll
        for (int nf = 0; nf < 4; nf++)
#pragma unroll
            for (int q = 0; q < 4; q++) c[ma][nf][q] = 0.0f;

    const int KT = K >> 5;

    auto issue = [&](int s, int kt) {
        __half* as = As_ + s*HSTAGE + lr*HSTRIDE + ho;
        __half* bs = Bs_ + s*HSTAGE + lr*HSTRIDE + ho;
        cp16(as,     Ap + kt*32);
        cp16(as + 8, Ap + kt*32 + 8);
        cp16(bs,     Wp + kt*32);
        cp16(bs + 8, Wp + kt*32 + 8);
    };

    issue(0, 0); CP_COMMIT();
    issue(1, 1); CP_COMMIT();
    CP_WAIT1();
    __syncthreads();

    for (int kt = 0; kt < KT; kt++) {
        const int cur = kt % 3;
        const __half* As = As_ + cur*HSTAGE;
        const __half* Bs = Bs_ + cur*HSTAGE;

#pragma unroll
        for (int kb = 0; kb < 2; kb++) {
            uint4 av[4];
#pragma unroll
            for (int ma = 0; ma < 4; ma++)
                av[ma] = ldsm4(&As[(wm*64 + ma*16 + l15)*HSTRIDE + kb*16 + lhi8]);
            unsigned bf[4][2];
#pragma unroll
            for (int np = 0; np < 2; np++) {
                uint4 bv = ldsm4(&Bs[(wn*32 + np*16 + bn)*HSTRIDE + kb*16 + bk]);
                bf[2*np][0]   = bv.x; bf[2*np][1]   = bv.y;
                bf[2*np+1][0] = bv.z; bf[2*np+1][1] = bv.w;
            }
#pragma unroll
            for (int ma = 0; ma < 4; ma++)
#pragma unroll
                for (int nf = 0; nf < 4; nf++)
                    MMA16(c[ma][nf], av[ma].x, av[ma].y, av[ma].z, av[ma].w,
                          bf[nf][0], bf[nf][1]);
        }

        if (kt + 2 < KT) issue((kt + 2) % 3, kt + 2);
        CP_COMMIT();
        CP_WAIT1();
        __syncthreads();
    }

#pragma unroll
    for (int ma = 0; ma < 4; ma++) {
#pragma unroll
        for (int nf = 0; nf < 4; nf++) {
            int col = bCol + wn*32 + nf*8 + 2*t;
            int row = bRow + wm*64 + ma*16 + g;
            float b0 = bias[col], b1 = bias[col+1];
            float v0 = c[ma][nf][0]+b0, v1 = c[ma][nf][1]+b1;
            float v2 = c[ma][nf][2]+b0, v3 = c[ma][nf][3]+b1;
            if (GELU) { v0=gelu_exact(v0); v1=gelu_exact(v1);
                        v2=gelu_exact(v2); v3=gelu_exact(v3); }
            if (HALF_OUT) {
                *(__half2*)&Ch[(size_t)row*N + col]     = __floats2half2_rn(v0, v1);
                *(__half2*)&Ch[(size_t)(row+8)*N + col] = __floats2half2_rn(v2, v3);
            } else {
                float2 p0 = {v0,v1}, p1 = {v2,v3};
                *(float2*)&Cf[(size_t)row*N + col]     = p0;
                *(float2*)&Cf[(size_t)(row+8)*N + col] = p1;
            }
        }
    }
}

// ---------------- fp16 flash attention ----------------
// grid (L/128, B*H), 256 thr = 8 warps, warp = 16 q-rows.
// smem halves, stride 72 (=144B, odd*16B): Qs[128][72], Ps[128][72],
// Ks[2][64][72], Vs[2][64][72]. K/V double-buffered via cp.async.
#define ASTRIDE 72
__global__ void __launch_bounds__(256)
attn_h(const __half* __restrict__ qkv, __half* __restrict__ outh) {
    extern __shared__ __half smh[];
    __half* Qs = smh;                       // 128*72
    __half* Ps = smh + 128*ASTRIDE;         // 128*72
    __half* Ks = smh + 2*128*ASTRIDE;       // 2*64*72
    __half* Vs = Ks + 2*64*ASTRIDE;         // 2*64*72

    const int tid = threadIdx.x, lane = tid & 31, warp = tid >> 5;
    const int g = lane >> 2, t = lane & 3;
    const int q0 = blockIdx.x * 128;
    const int b = blockIdx.y >> 3, h = blockIdx.y & 7;
    const int w16 = warp * 16;
    const int l15 = lane & 15, lhi8 = (lane >> 4) << 3;
    const int bn = (lane & 7) + ((lane & 16) >> 1);
    const int bk = lane & 8;
    const size_t qoff = h*64, koff = 512 + h*64, voff = 1024 + h*64;

    // Q tile (direct vectorized copy, fp16)
    for (int i = tid; i < 128*8; i += 256) {
        int r = i >> 3, c = (i & 7) * 8;
        *(uint4*)&Qs[r*ASTRIDE + c] =
            *(const uint4*)&qkv[((size_t)((q0+r)*BB + b))*1536 + qoff + c];
    }

    auto issue = [&](int s, int kt) {
        int k0 = kt * 64;
#pragma unroll
        for (int j = 0; j < 4; j++) {
            int i = tid + j*256;
            int kv = i >> 9, r = (i >> 3) & 63, c = (i & 7) * 8;
            __half* dst = (kv ? Vs : Ks) + s*64*ASTRIDE + r*ASTRIDE + c;
            const __half* src = qkv + ((size_t)((k0+r)*BB + b))*1536 + (kv ? voff : koff) + c;
            cp16(dst, src);
        }
    };

    issue(0, 0); CP_COMMIT();

    float m_[2] = {-1e30f, -1e30f}, l_[2] = {0.0f, 0.0f};
    float o[8][4];
#pragma unroll
    for (int nf = 0; nf < 8; nf++)
#pragma unroll
        for (int q = 0; q < 4; q++) o[nf][q] = 0.0f;

    const int NT = LL/64;
    for (int kt = 0; kt < NT; kt++) {
        const int cur = kt & 1;
        if (kt + 1 < NT) issue(cur ^ 1, kt + 1);
        CP_COMMIT();
        CP_WAIT1();
        __syncthreads();

        const __half* Kc = Ks + cur*64*ASTRIDE;
        const __half* Vc = Vs + cur*64*ASTRIDE;

        // S = Q K^T / 8
        float s_[8][4];
#pragma unroll
        for (int nf = 0; nf < 8; nf++)
#pragma unroll
            for (int q = 0; q < 4; q++) s_[nf][q] = 0.0f;

#pragma unroll
        for (int kb = 0; kb < 4; kb++) {
            uint4 av = ldsm4(&Qs[(w16 + l15)*ASTRIDE + kb*16 + lhi8]);
            unsigned bf[8][2];
#pragma unroll
            for (int np = 0; np < 4; np++) {
                uint4 bv = ldsm4(&Kc[(np*16 + bn)*ASTRIDE + kb*16 + bk]);
                bf[2*np][0]   = bv.x; bf[2*np][1]   = bv.y;
                bf[2*np+1][0] = bv.z; bf[2*np+1][1] = bv.w;
            }
#pragma unroll
            for (int nf = 0; nf < 8; nf++)
                MMA16(s_[nf], av.x, av.y, av.z, av.w, bf[nf][0], bf[nf][1]);
        }

        // online softmax (rows g, g+8; reduce over 4-lane t-group)
#pragma unroll
        for (int hf = 0; hf < 2; hf++) {
            float mx = -1e30f;
#pragma unroll
            for (int nf = 0; nf < 8; nf++) {
                s_[nf][2*hf]   *= 0.125f;
                s_[nf][2*hf+1] *= 0.125f;
                mx = fmaxf(mx, fmaxf(s_[nf][2*hf], s_[nf][2*hf+1]));
            }
            mx = fmaxf(mx, __shfl_xor_sync(0xffffffffu, mx, 1));
            mx = fmaxf(mx, __shfl_xor_sync(0xffffffffu, mx, 2));
            float mn = fmaxf(m_[hf], mx);
            float sc = __expf(m_[hf] - mn);
            float rs = 0.0f;
#pragma unroll
            for (int nf = 0; nf < 8; nf++) {
                s_[nf][2*hf]   = __expf(s_[nf][2*hf]   - mn);
                s_[nf][2*hf+1] = __expf(s_[nf][2*hf+1] - mn);
                rs += s_[nf][2*hf] + s_[nf][2*hf+1];
            }
            rs += __shfl_xor_sync(0xffffffffu, rs, 1);
            rs += __shfl_xor_sync(0xffffffffu, rs, 2);
            l_[hf] = l_[hf] * sc + rs;
#pragma unroll
            for (int nf = 0; nf < 8; nf++) {
                o[nf][2*hf] *= sc; o[nf][2*hf+1] *= sc;
            }
            m_[hf] = mn;
        }

        // P -> smem (warp-private rows), fp16
#pragma unroll
        for (int nf = 0; nf < 8; nf++) {
            *(__half2*)&Ps[(w16+g)*ASTRIDE + nf*8 + 2*t]   = __floats2half2_rn(s_[nf][0], s_[nf][1]);
            *(__half2*)&Ps[(w16+g+8)*ASTRIDE + nf*8 + 2*t] = __floats2half2_rn(s_[nf][2], s_[nf][3]);
        }
        __syncwarp();

        // O += P V  (V^T fragments via ldmatrix.trans)
#pragma unroll
        for (int kb = 0; kb < 4; kb++) {
            uint4 av = ldsm4(&Ps[(w16 + l15)*ASTRIDE + kb*16 + lhi8]);
            unsigned bf[8][2];
#pragma unroll
            for (int df = 0; df < 4; df++) {
                uint4 bv = ldsm4t(&Vc[(kb*16 + l15)*ASTRIDE + df*16 + lhi8]);
                bf[2*df][0]   = bv.x; bf[2*df][1]   = bv.y;
                bf[2*df+1][0] = bv.z; bf[2*df+1][1] = bv.w;
            }
#pragma unroll
            for (int nf = 0; nf < 8; nf++)
                MMA16(o[nf], av.x, av.y, av.z, av.w, bf[nf][0], bf[nf][1]);
        }
        __syncthreads();   // stage safe for next issue
    }

#pragma unroll
    for (int hf = 0; hf < 2; hf++) {
        float inv = 1.0f / l_[hf];
        int row = q0 + w16 + g + 8*hf;
        size_t base = ((size_t)row*BB + b)*512 + h*64;
#pragma unroll
        for (int nf = 0; nf < 8; nf++)
            *(__half2*)&outh[base + nf*8 + 2*t] =
                __floats2half2_rn(o[nf][2*hf]*inv, o[nf][2*hf+1]*inv);
    }
}

// ---------------- residual add + layernorm (optional fp16 copy) -----------
template<int WH>
__global__ void __launch_bounds__(256)
add_ln_kernel(const float* __restrict__ a, const float* __restrict__ r,
              const float* __restrict__ g, const float* __restrict__ beta,
              float* __restrict__ out, __half* __restrict__ outh) {
    __shared__ float red[8];
    int t = blockIdx.x;
    int tid = threadIdx.x;
    const float* pa = a + (size_t)t * EE;
    const float* pr = r + (size_t)t * EE;
    float v0 = pa[tid] + pr[tid];
    float v1 = pa[tid + 256] + pr[tid + 256];
    float sum = v0 + v1;
#pragma unroll
    for (int off = 16; off > 0; off >>= 1)
        sum += __shfl_xor_sync(0xffffffffu, sum, off);
    if ((tid & 31) == 0) red[tid >> 5] = sum;
    __syncthreads();
    float tot = 0.0f;
#pragma unroll
    for (int w = 0; w < 8; w++) tot += red[w];
    float mu = tot * (1.0f / 512.0f);
    __syncthreads();
    float d0 = v0 - mu, d1 = v1 - mu;
    float sq = d0*d0 + d1*d1;
#pragma unroll
    for (int off = 16; off > 0; off >>= 1)
        sq += __shfl_xor_sync(0xffffffffu, sq, off);
    if ((tid & 31) == 0) red[tid >> 5] = sq;
    __syncthreads();
    float vt = 0.0f;
#pragma unroll
    for (int w = 0; w < 8; w++) vt += red[w];
    float rstd = rsqrtf(vt * (1.0f / 512.0f) + 1e-5f);
    float o0 = d0 * rstd * g[tid]       + beta[tid];
    float o1 = d1 * rstd * g[tid + 256] + beta[tid + 256];
    out[(size_t)t*EE + tid]       = o0;
    out[(size_t)t*EE + tid + 256] = o1;
    if (WH) {
        outh[(size_t)t*EE + tid]       = __float2half_rn(o0);
        outh[(size_t)t*EE + tid + 256] = __float2half_rn(o1);
    }
}

// ---------------- launch ----------------
extern "C" void kernel_launch(void* const* d_in, const int* in_sizes, int n_in,
                              void* d_out, int out_size) {
    const float* x     = (const float*)d_in[0];
    const float* in_w  = (const float*)d_in[1];
    const float* in_b  = (const float*)d_in[2];
    const float* out_w = (const float*)d_in[3];
    const float* out_b = (const float*)d_in[4];
    const float* w1    = (const float*)d_in[5];
    const float* b1    = (const float*)d_in[6];
    const float* w2    = (const float*)d_in[7];
    const float* b2    = (const float*)d_in[8];
    const float* ln_g  = (const float*)d_in[9];
    const float* ln_b  = (const float*)d_in[10];
    float* out = (float*)d_out;

    float *x0, *proj, *x1, *ff;
    __half *x0h, *qkvh, *atth, *x1h, *hh, *wh;
    cudaGetSymbolAddress((void**)&x0,   g_x0);
    cudaGetSymbolAddress((void**)&proj, g_proj);
    cudaGetSymbolAddress((void**)&x1,   g_x1);
    cudaGetSymbolAddress((void**)&ff,   g_ff);
    cudaGetSymbolAddress((void**)&x0h,  g_x0h);
    cudaGetSymbolAddress((void**)&qkvh, g_qkvh);
    cudaGetSymbolAddress((void**)&atth, g_atth);
    cudaGetSymbolAddress((void**)&x1h,  g_x1h);
    cudaGetSymbolAddress((void**)&hh,   g_hh);
    cudaGetSymbolAddress((void**)&wh,   g_wh);

    const int gemm_smem = 6 * HSTAGE * (int)sizeof(__half);            // 61440
    const int attn_smem = (2*128 + 4*64) * ASTRIDE * (int)sizeof(__half); // 73728
    cudaFuncSetAttribute(gemm_h<0,0>, cudaFuncAttributeMaxDynamicSharedMemorySize, gemm_smem);
    cudaFuncSetAttribute(gemm_h<0,1>, cudaFuncAttributeMaxDynamicSharedMemorySize, gemm_smem);
    cudaFuncSetAttribute(gemm_h<1,1>, cudaFuncAttributeMaxDynamicSharedMemorySize, gemm_smem);
    cudaFuncSetAttribute(attn_h, cudaFuncAttributeMaxDynamicSharedMemorySize, attn_smem);

    // weights -> fp16 (every call; deterministic)
    f2h_kernel<<<(786432+255)/256, 256>>>(in_w,  wh + WOFF_IN,  786432);
    f2h_kernel<<<(262144+255)/256, 256>>>(out_w, wh + WOFF_OUT, 262144);
    f2h_kernel<<<(1048576+255)/256, 256>>>(w1,   wh + WOFF_W1,  1048576);
    f2h_kernel<<<(1048576+255)/256, 256>>>(w2,   wh + WOFF_W2,  1048576);

    pe_add_kernel<<<(TT*EE)/256, 256>>>(x, x0, x0h);
    gemm_h<0,1><<<dim3(1536/128, TT/128), 256, gemm_smem>>>(x0h, wh + WOFF_IN, in_b, nullptr, qkvh, 1536, 512);
    attn_h<<<dim3(LL/128, BB*HH), 256, attn_smem>>>(qkvh, atth);
    gemm_h<0,0><<<dim3(512/128, TT/128), 256, gemm_smem>>>(atth, wh + WOFF_OUT, out_b, proj, nullptr, 512, 512);
    add_ln_kernel<1><<<TT, 256>>>(proj, x0, ln_g, ln_b, x1, x1h);
    gemm_h<1,1><<<dim3(2048/128, TT/128), 256, gemm_smem>>>(x1h, wh + WOFF_W1, b1, nullptr, hh, 2048, 512);
    gemm_h<0,0><<<dim3(512/128, TT/128), 256, gemm_smem>>>(hh, wh + WOFF_W2, b2, ff, nullptr, 512, 2048);
    add_ln_kernel<0><<<TT, 256>>>(ff, x1, ln_g, ln_b, out, nullptr);
}

// round 12
// speedup vs baseline: 5.9176x; 1.0642x over previous
#include <cuda_runtime.h>
#include <cuda_fp16.h>
#include <math.h>
#include <stdint.h>

#define LL 2048
#define BB 4
#define EE 512
#define HH 8
#define TT (LL*BB)

// ---------------- scratch ----------------
__device__ float  g_x0 [TT*EE];
__device__ float  g_proj[TT*EE];
__device__ float  g_x1 [TT*EE];
__device__ float  g_ff [TT*EE];
__device__ __half g_x0h [TT*EE];
__device__ __half g_qkvh[TT*3*EE];
__device__ __half g_atth[TT*EE];
__device__ __half g_x1h [TT*EE];
__device__ __half g_hh  [TT*2048];
__device__ __half g_wh  [3145728];   // in_w | out_w | w1 | w2
#define WOFF_IN  0
#define WOFF_OUT 786432
#define WOFF_W1  1048576
#define WOFF_W2  2097152

// ---------------- helpers ----------------
__device__ __forceinline__ float gelu_exact(float v) {
    return 0.5f * v * (1.0f + erff(v * 0.70710678118654752f));
}
__device__ __forceinline__ void cp16(void* smem_dst, const void* gsrc) {
    unsigned s = (unsigned)__cvta_generic_to_shared(smem_dst);
    asm volatile("cp.async.cg.shared.global [%0], [%1], 16;" :: "r"(s), "l"(gsrc));
}
#define CP_COMMIT() asm volatile("cp.async.commit_group;")
#define CP_WAIT1()  asm volatile("cp.async.wait_group 1;")

__device__ __forceinline__ uint4 ldsm4(const void* p) {
    unsigned s = (unsigned)__cvta_generic_to_shared(p);
    uint4 v;
    asm volatile("ldmatrix.sync.aligned.m8n8.x4.shared.b16 {%0,%1,%2,%3}, [%4];"
                 : "=r"(v.x), "=r"(v.y), "=r"(v.z), "=r"(v.w) : "r"(s));
    return v;
}
__device__ __forceinline__ uint4 ldsm4t(const void* p) {
    unsigned s = (unsigned)__cvta_generic_to_shared(p);
    uint4 v;
    asm volatile("ldmatrix.sync.aligned.m8n8.x4.trans.shared.b16 {%0,%1,%2,%3}, [%4];"
                 : "=r"(v.x), "=r"(v.y), "=r"(v.z), "=r"(v.w) : "r"(s));
    return v;
}
#define MMA16(c, a0,a1,a2,a3, b0,b1) asm volatile( \
    "mma.sync.aligned.m16n8k16.row.col.f32.f16.f16.f32 " \
    "{%0,%1,%2,%3}, {%4,%5,%6,%7}, {%8,%9}, {%0,%1,%2,%3};\n" \
    : "+f"((c)[0]), "+f"((c)[1]), "+f"((c)[2]), "+f"((c)[3]) \
    : "r"(a0), "r"(a1), "r"(a2), "r"(a3), "r"(b0), "r"(b1))

// ---------------- fused weight convert: all four weights, float4 ----------
// element count total 3145728 floats = 786432 float4s.
__global__ void __launch_bounds__(256)
f2h_all(const float* __restrict__ w_in, const float* __restrict__ w_out,
        const float* __restrict__ w1, const float* __restrict__ w2,
        __half* __restrict__ dst) {
    int i = blockIdx.x * blockDim.x + threadIdx.x;   // float4 index
    if (i >= 786432) return;
    const float* src;
    int base;
    if (i < 196608)      { src = w_in;  base = 0;      }
    else if (i < 262144) { src = w_out; base = 196608; }
    else if (i < 524288) { src = w1;    base = 262144; }
    else                 { src = w2;    base = 524288; }
    float4 v = ((const float4*)src)[i - base];
    __half2 h0 = __floats2half2_rn(v.x, v.y);
    __half2 h1 = __floats2half2_rn(v.z, v.w);
    uint2 pk = { *(unsigned*)&h0, *(unsigned*)&h1 };
    ((uint2*)dst)[i] = pk;
}

// ---------------- PE add, vectorized ----------------
__global__ void __launch_bounds__(256)
pe_add_kernel(const float* __restrict__ x, float* __restrict__ out,
              __half* __restrict__ outh) {
    int i = blockIdx.x * blockDim.x + threadIdx.x;   // float4 index
    if (i >= TT*EE/4) return;
    int e4 = (i & (EE/4 - 1)) * 4;
    int b = (i / (EE/4)) & (BB - 1);
    float4 v = ((const float4*)x)[i];
    float pe[4];
#pragma unroll
    for (int j = 0; j < 4; j++) {
        int e = e4 + j;
        float ef = (e & 1) ? (float)(e + 1) : (float)e;
        float freq = __expf(-ef * (9.210340371976184f / 512.0f));
        float arg = (float)(b + 1) * freq;
        pe[j] = (e & 1) ? cosf(arg) : sinf(arg);
    }
    float4 o = {v.x + pe[0], v.y + pe[1], v.z + pe[2], v.w + pe[3]};
    ((float4*)out)[i] = o;
    __half2 h0 = __floats2half2_rn(o.x, o.y);
    __half2 h1 = __floats2half2_rn(o.z, o.w);
    uint2 pk = { *(unsigned*)&h0, *(unsigned*)&h1 };
    ((uint2*)outh)[i] = pk;
}

// ---------------- fp16 GEMM, 3-stage cp.async, ldmatrix -----------------
#define HSTRIDE 40
#define HSTAGE  (128*HSTRIDE)

template<int GELU, int HALF_OUT>
__global__ void __launch_bounds__(256)
gemm_h(const __half* __restrict__ A, const __half* __restrict__ W,
       const float* __restrict__ bias, float* __restrict__ Cf,
       __half* __restrict__ Ch, int N, int K) {
    extern __shared__ __half smh[];
    __half* As_ = smh;
    __half* Bs_ = smh + 3*HSTAGE;

    const int tid = threadIdx.x, lane = tid & 31, warp = tid >> 5;
    const int g = lane >> 2, t = lane & 3;
    const int wm = warp >> 2, wn = warp & 3;
    const int bRow = blockIdx.y * 128, bCol = blockIdx.x * 128;
    const int lr = tid >> 1, ho = (tid & 1) * 16;
    const int l15 = lane & 15, lhi8 = (lane >> 4) << 3;
    const int bn = (lane & 7) + ((lane & 16) >> 1);
    const int bk = lane & 8;

    const __half* Ap = A + (size_t)(bRow + lr) * K + ho;
    const __half* Wp = W + (size_t)(bCol + lr) * K + ho;

    float c[4][4][4];
#pragma unroll
    for (int ma = 0; ma < 4; ma++)
#pragma unroll
        for (int nf = 0; nf < 4; nf++)
#pragma unroll
            for (int q = 0; q < 4; q++) c[ma][nf][q] = 0.0f;

    const int KT = K >> 5;

    auto issue = [&](int s, int kt) {
        __half* as = As_ + s*HSTAGE + lr*HSTRIDE + ho;
        __half* bs = Bs_ + s*HSTAGE + lr*HSTRIDE + ho;
        cp16(as,     Ap + kt*32);
        cp16(as + 8, Ap + kt*32 + 8);
        cp16(bs,     Wp + kt*32);
        cp16(bs + 8, Wp + kt*32 + 8);
    };

    issue(0, 0); CP_COMMIT();
    issue(1, 1); CP_COMMIT();
    CP_WAIT1();
    __syncthreads();

    for (int kt = 0; kt < KT; kt++) {
        const int cur = kt % 3;
        const __half* As = As_ + cur*HSTAGE;
        const __half* Bs = Bs_ + cur*HSTAGE;

#pragma unroll
        for (int kb = 0; kb < 2; kb++) {
            uint4 av[4];
#pragma unroll
            for (int ma = 0; ma < 4; ma++)
                av[ma] = ldsm4(&As[(wm*64 + ma*16 + l15)*HSTRIDE + kb*16 + lhi8]);
            unsigned bf[4][2];
#pragma unroll
            for (int np = 0; np < 2; np++) {
                uint4 bv = ldsm4(&Bs[(wn*32 + np*16 + bn)*HSTRIDE + kb*16 + bk]);
                bf[2*np][0]   = bv.x; bf[2*np][1]   = bv.y;
                bf[2*np+1][0] = bv.z; bf[2*np+1][1] = bv.w;
            }
#pragma unroll
            for (int ma = 0; ma < 4; ma++)
#pragma unroll
                for (int nf = 0; nf < 4; nf++)
                    MMA16(c[ma][nf], av[ma].x, av[ma].y, av[ma].z, av[ma].w,
                          bf[nf][0], bf[nf][1]);
        }

        if (kt + 2 < KT) issue((kt + 2) % 3, kt + 2);
        CP_COMMIT();
        CP_WAIT1();
        __syncthreads();
    }

#pragma unroll
    for (int ma = 0; ma < 4; ma++) {
#pragma unroll
        for (int nf = 0; nf < 4; nf++) {
            int col = bCol + wn*32 + nf*8 + 2*t;
            int row = bRow + wm*64 + ma*16 + g;
            float b0 = bias[col], b1 = bias[col+1];
            float v0 = c[ma][nf][0]+b0, v1 = c[ma][nf][1]+b1;
            float v2 = c[ma][nf][2]+b0, v3 = c[ma][nf][3]+b1;
            if (GELU) { v0=gelu_exact(v0); v1=gelu_exact(v1);
                        v2=gelu_exact(v2); v3=gelu_exact(v3); }
            if (HALF_OUT) {
                *(__half2*)&Ch[(size_t)row*N + col]     = __floats2half2_rn(v0, v1);
                *(__half2*)&Ch[(size_t)(row+8)*N + col] = __floats2half2_rn(v2, v3);
            } else {
                float2 p0 = {v0,v1}, p1 = {v2,v3};
                *(float2*)&Cf[(size_t)row*N + col]     = p0;
                *(float2*)&Cf[(size_t)(row+8)*N + col] = p1;
            }
        }
    }
}

// ---------------- fp16 flash attention ----------------
#define ASTRIDE 72
__global__ void __launch_bounds__(256)
attn_h(const __half* __restrict__ qkv, __half* __restrict__ outh) {
    extern __shared__ __half smh[];
    __half* Qs = smh;
    __half* Ps = smh + 128*ASTRIDE;
    __half* Ks = smh + 2*128*ASTRIDE;
    __half* Vs = Ks + 2*64*ASTRIDE;

    const int tid = threadIdx.x, lane = tid & 31, warp = tid >> 5;
    const int g = lane >> 2, t = lane & 3;
    const int q0 = blockIdx.x * 128;
    const int b = blockIdx.y >> 3, h = blockIdx.y & 7;
    const int w16 = warp * 16;
    const int l15 = lane & 15, lhi8 = (lane >> 4) << 3;
    const int bn = (lane & 7) + ((lane & 16) >> 1);
    const int bk = lane & 8;
    const size_t qoff = h*64, koff = 512 + h*64, voff = 1024 + h*64;

    for (int i = tid; i < 128*8; i += 256) {
        int r = i >> 3, c = (i & 7) * 8;
        *(uint4*)&Qs[r*ASTRIDE + c] =
            *(const uint4*)&qkv[((size_t)((q0+r)*BB + b))*1536 + qoff + c];
    }

    auto issue = [&](int s, int kt) {
        int k0 = kt * 64;
#pragma unroll
        for (int j = 0; j < 4; j++) {
            int i = tid + j*256;
            int kv = i >> 9, r = (i >> 3) & 63, c = (i & 7) * 8;
            __half* dst = (kv ? Vs : Ks) + s*64*ASTRIDE + r*ASTRIDE + c;
            const __half* src = qkv + ((size_t)((k0+r)*BB + b))*1536 + (kv ? voff : koff) + c;
            cp16(dst, src);
        }
    };

    issue(0, 0); CP_COMMIT();

    float m_[2] = {-1e30f, -1e30f}, l_[2] = {0.0f, 0.0f};
    float o[8][4];
#pragma unroll
    for (int nf = 0; nf < 8; nf++)
#pragma unroll
        for (int q = 0; q < 4; q++) o[nf][q] = 0.0f;

    const int NT = LL/64;
    for (int kt = 0; kt < NT; kt++) {
        const int cur = kt & 1;
        if (kt + 1 < NT) issue(cur ^ 1, kt + 1);
        CP_COMMIT();
        CP_WAIT1();
        __syncthreads();

        const __half* Kc = Ks + cur*64*ASTRIDE;
        const __half* Vc = Vs + cur*64*ASTRIDE;

        float s_[8][4];
#pragma unroll
        for (int nf = 0; nf < 8; nf++)
#pragma unroll
            for (int q = 0; q < 4; q++) s_[nf][q] = 0.0f;

#pragma unroll
        for (int kb = 0; kb < 4; kb++) {
            uint4 av = ldsm4(&Qs[(w16 + l15)*ASTRIDE + kb*16 + lhi8]);
            unsigned bf[8][2];
#pragma unroll
            for (int np = 0; np < 4; np++) {
                uint4 bv = ldsm4(&Kc[(np*16 + bn)*ASTRIDE + kb*16 + bk]);
                bf[2*np][0]   = bv.x; bf[2*np][1]   = bv.y;
                bf[2*np+1][0] = bv.z; bf[2*np+1][1] = bv.w;
            }
#pragma unroll
            for (int nf = 0; nf < 8; nf++)
                MMA16(s_[nf], av.x, av.y, av.z, av.w, bf[nf][0], bf[nf][1]);
        }

#pragma unroll
        for (int hf = 0; hf < 2; hf++) {
            float mx = -1e30f;
#pragma unroll
            for (int nf = 0; nf < 8; nf++) {
                s_[nf][2*hf]   *= 0.125f;
                s_[nf][2*hf+1] *= 0.125f;
                mx = fmaxf(mx, fmaxf(s_[nf][2*hf], s_[nf][2*hf+1]));
            }
            mx = fmaxf(mx, __shfl_xor_sync(0xffffffffu, mx, 1));
            mx = fmaxf(mx, __shfl_xor_sync(0xffffffffu, mx, 2));
            float mn = fmaxf(m_[hf], mx);
            float sc = __expf(m_[hf] - mn);
            float rs = 0.0f;
#pragma unroll
            for (int nf = 0; nf < 8; nf++) {
                s_[nf][2*hf]   = __expf(s_[nf][2*hf]   - mn);
                s_[nf][2*hf+1] = __expf(s_[nf][2*hf+1] - mn);
                rs += s_[nf][2*hf] + s_[nf][2*hf+1];
            }
            rs += __shfl_xor_sync(0xffffffffu, rs, 1);
            rs += __shfl_xor_sync(0xffffffffu, rs, 2);
            l_[hf] = l_[hf] * sc + rs;
#pragma unroll
            for (int nf = 0; nf < 8; nf++) {
                o[nf][2*hf] *= sc; o[nf][2*hf+1] *= sc;
            }
            m_[hf] = mn;
        }

#pragma unroll
        for (int nf = 0; nf < 8; nf++) {
            *(__half2*)&Ps[(w16+g)*ASTRIDE + nf*8 + 2*t]   = __floats2half2_rn(s_[nf][0], s_[nf][1]);
            *(__half2*)&Ps[(w16+g+8)*ASTRIDE + nf*8 + 2*t] = __floats2half2_rn(s_[nf][2], s_[nf][3]);
        }
        __syncwarp();

#pragma unroll
        for (int kb = 0; kb < 4; kb++) {
            uint4 av = ldsm4(&Ps[(w16 + l15)*ASTRIDE + kb*16 + lhi8]);
            unsigned bf[8][2];
#pragma unroll
            for (int df = 0; df < 4; df++) {
                uint4 bv = ldsm4t(&Vc[(kb*16 + l15)*ASTRIDE + df*16 + lhi8]);
                bf[2*df][0]   = bv.x; bf[2*df][1]   = bv.y;
                bf[2*df+1][0] = bv.z; bf[2*df+1][1] = bv.w;
            }
#pragma unroll
            for (int nf = 0; nf < 8; nf++)
                MMA16(o[nf], av.x, av.y, av.z, av.w, bf[nf][0], bf[nf][1]);
        }
        __syncthreads();
    }

#pragma unroll
    for (int hf = 0; hf < 2; hf++) {
        float inv = 1.0f / l_[hf];
        int row = q0 + w16 + g + 8*hf;
        size_t base = ((size_t)row*BB + b)*512 + h*64;
#pragma unroll
        for (int nf = 0; nf < 8; nf++)
            *(__half2*)&outh[base + nf*8 + 2*t] =
                __floats2half2_rn(o[nf][2*hf]*inv, o[nf][2*hf+1]*inv);
    }
}

// ---------------- residual add + layernorm, vectorized ----------------
// 128 threads per token; each thread one float4 (E=512).
template<int WH>
__global__ void __launch_bounds__(128)
add_ln_kernel(const float* __restrict__ a, const float* __restrict__ r,
              const float* __restrict__ g, const float* __restrict__ beta,
              float* __restrict__ out, __half* __restrict__ outh) {
    __shared__ float red[4];
    int t = blockIdx.x;
    int tid = threadIdx.x;
    float4 va = ((const float4*)(a + (size_t)t*EE))[tid];
    float4 vr = ((const float4*)(r + (size_t)t*EE))[tid];
    float4 v = {va.x+vr.x, va.y+vr.y, va.z+vr.z, va.w+vr.w};

    float sum = v.x + v.y + v.z + v.w;
#pragma unroll
    for (int off = 16; off > 0; off >>= 1)
        sum += __shfl_xor_sync(0xffffffffu, sum, off);
    if ((tid & 31) == 0) red[tid >> 5] = sum;
    __syncthreads();
    float mu = (red[0] + red[1] + red[2] + red[3]) * (1.0f / 512.0f);
    __syncthreads();

    float4 d = {v.x-mu, v.y-mu, v.z-mu, v.w-mu};
    float sq = d.x*d.x + d.y*d.y + d.z*d.z + d.w*d.w;
#pragma unroll
    for (int off = 16; off > 0; off >>= 1)
        sq += __shfl_xor_sync(0xffffffffu, sq, off);
    if ((tid & 31) == 0) red[tid >> 5] = sq;
    __syncthreads();
    float rstd = rsqrtf((red[0]+red[1]+red[2]+red[3]) * (1.0f/512.0f) + 1e-5f);

    float4 gg = ((const float4*)g)[tid];
    float4 bb = ((const float4*)beta)[tid];
    float4 o = {d.x*rstd*gg.x + bb.x, d.y*rstd*gg.y + bb.y,
                d.z*rstd*gg.z + bb.z, d.w*rstd*gg.w + bb.w};
    ((float4*)(out + (size_t)t*EE))[tid] = o;
    if (WH) {
        __half2 h0 = __floats2half2_rn(o.x, o.y);
        __half2 h1 = __floats2half2_rn(o.z, o.w);
        uint2 pk = { *(unsigned*)&h0, *(unsigned*)&h1 };
        ((uint2*)(outh + (size_t)t*EE))[tid] = pk;
    }
}

// ---------------- launch ----------------
extern "C" void kernel_launch(void* const* d_in, const int* in_sizes, int n_in,
                              void* d_out, int out_size) {
    const float* x     = (const float*)d_in[0];
    const float* in_w  = (const float*)d_in[1];
    const float* in_b  = (const float*)d_in[2];
    const float* out_w = (const float*)d_in[3];
    const float* out_b = (const float*)d_in[4];
    const float* w1    = (const float*)d_in[5];
    const float* b1    = (const float*)d_in[6];
    const float* w2    = (const float*)d_in[7];
    const float* b2    = (const float*)d_in[8];
    const float* ln_g  = (const float*)d_in[9];
    const float* ln_b  = (const float*)d_in[10];
    float* out = (float*)d_out;

    float *x0, *proj, *x1, *ff;
    __half *x0h, *qkvh, *atth, *x1h, *hh, *wh;
    cudaGetSymbolAddress((void**)&x0,   g_x0);
    cudaGetSymbolAddress((void**)&proj, g_proj);
    cudaGetSymbolAddress((void**)&x1,   g_x1);
    cudaGetSymbolAddress((void**)&ff,   g_ff);
    cudaGetSymbolAddress((void**)&x0h,  g_x0h);
    cudaGetSymbolAddress((void**)&qkvh, g_qkvh);
    cudaGetSymbolAddress((void**)&atth, g_atth);
    cudaGetSymbolAddress((void**)&x1h,  g_x1h);
    cudaGetSymbolAddress((void**)&hh,   g_hh);
    cudaGetSymbolAddress((void**)&wh,   g_wh);

    const int gemm_smem = 6 * HSTAGE * (int)sizeof(__half);
    const int attn_smem = (2*128 + 4*64) * ASTRIDE * (int)sizeof(__half);
    cudaFuncSetAttribute(gemm_h<0,0>, cudaFuncAttributeMaxDynamicSharedMemorySize, gemm_smem);
    cudaFuncSetAttribute(gemm_h<0,1>, cudaFuncAttributeMaxDynamicSharedMemorySize, gemm_smem);
    cudaFuncSetAttribute(gemm_h<1,1>, cudaFuncAttributeMaxDynamicSharedMemorySize, gemm_smem);
    cudaFuncSetAttribute(attn_h, cudaFuncAttributeMaxDynamicSharedMemorySize, attn_smem);

    f2h_all<<<(786432 + 255)/256, 256>>>(in_w, out_w, w1, w2, wh);
    pe_add_kernel<<<(TT*EE/4 + 255)/256, 256>>>(x, x0, x0h);
    gemm_h<0,1><<<dim3(1536/128, TT/128), 256, gemm_smem>>>(x0h, wh + WOFF_IN, in_b, nullptr, qkvh, 1536, 512);
    attn_h<<<dim3(LL/128, BB*HH), 256, attn_smem>>>(qkvh, atth);
    gemm_h<0,0><<<dim3(512/128, TT/128), 256, gemm_smem>>>(atth, wh + WOFF_OUT, out_b, proj, nullptr, 512, 512);
    add_ln_kernel<1><<<TT, 128>>>(proj, x0, ln_g, ln_b, x1, x1h);
    gemm_h<1,1><<<dim3(2048/128, TT/128), 256, gemm_smem>>>(x1h, wh + WOFF_W1, b1, nullptr, hh, 2048, 512);
    gemm_h<0,0><<<dim3(512/128, TT/128), 256, gemm_smem>>>(hh, wh + WOFF_W2, b2, ff, nullptr, 512, 2048);
    add_ln_kernel<0><<<TT, 128>>>(ff, x1, ln_g, ln_b, out, nullptr);
}

// round 13
// speedup vs baseline: 6.1346x; 1.0367x over previous
#include <cuda_runtime.h>
#include <cuda_fp16.h>
#include <math.h>
#include <stdint.h>

#define LL 2048
#define BB 4
#define EE 512
#define HH 8
#define TT (LL*BB)

// ---------------- scratch ----------------
__device__ float  g_x0 [TT*EE];
__device__ float  g_proj[TT*EE];
__device__ float  g_x1 [TT*EE];
__device__ float  g_ff [TT*EE];
__device__ __half g_x0h [TT*EE];
__device__ __half g_qkvh[TT*3*EE];
__device__ __half g_atth[TT*EE];
__device__ __half g_x1h [TT*EE];
__device__ __half g_hh  [TT*2048];
__device__ __half g_wh  [3145728];   // in_w | out_w | w1 | w2
#define WOFF_IN  0
#define WOFF_OUT 786432
#define WOFF_W1  1048576
#define WOFF_W2  2097152

// ---------------- helpers ----------------
__device__ __forceinline__ float gelu_exact(float v) {
    return 0.5f * v * (1.0f + erff(v * 0.70710678118654752f));
}
__device__ __forceinline__ float ex2f(float x) {
    float y; asm("ex2.approx.f32 %0, %1;" : "=f"(y) : "f"(x)); return y;
}
__device__ __forceinline__ void cp16(void* smem_dst, const void* gsrc) {
    unsigned s = (unsigned)__cvta_generic_to_shared(smem_dst);
    asm volatile("cp.async.cg.shared.global [%0], [%1], 16;" :: "r"(s), "l"(gsrc));
}
#define CP_COMMIT() asm volatile("cp.async.commit_group;")
#define CP_WAIT1()  asm volatile("cp.async.wait_group 1;")

__device__ __forceinline__ uint4 ldsm4(const void* p) {
    unsigned s = (unsigned)__cvta_generic_to_shared(p);
    uint4 v;
    asm volatile("ldmatrix.sync.aligned.m8n8.x4.shared.b16 {%0,%1,%2,%3}, [%4];"
                 : "=r"(v.x), "=r"(v.y), "=r"(v.z), "=r"(v.w) : "r"(s));
    return v;
}
__device__ __forceinline__ uint4 ldsm4t(const void* p) {
    unsigned s = (unsigned)__cvta_generic_to_shared(p);
    uint4 v;
    asm volatile("ldmatrix.sync.aligned.m8n8.x4.trans.shared.b16 {%0,%1,%2,%3}, [%4];"
                 : "=r"(v.x), "=r"(v.y), "=r"(v.z), "=r"(v.w) : "r"(s));
    return v;
}
#define MMA16(c, a0,a1,a2,a3, b0,b1) asm volatile( \
    "mma.sync.aligned.m16n8k16.row.col.f32.f16.f16.f32 " \
    "{%0,%1,%2,%3}, {%4,%5,%6,%7}, {%8,%9}, {%0,%1,%2,%3};\n" \
    : "+f"((c)[0]), "+f"((c)[1]), "+f"((c)[2]), "+f"((c)[3]) \
    : "r"(a0), "r"(a1), "r"(a2), "r"(a3), "r"(b0), "r"(b1))

// ---------------- fused weight convert ----------------
__global__ void __launch_bounds__(256)
f2h_all(const float* __restrict__ w_in, const float* __restrict__ w_out,
        const float* __restrict__ w1, const float* __restrict__ w2,
        __half* __restrict__ dst) {
    int i = blockIdx.x * blockDim.x + threadIdx.x;
    if (i >= 786432) return;
    const float* src;
    int base;
    if (i < 196608)      { src = w_in;  base = 0;      }
    else if (i < 262144) { src = w_out; base = 196608; }
    else if (i < 524288) { src = w1;    base = 262144; }
    else                 { src = w2;    base = 524288; }
    float4 v = ((const float4*)src)[i - base];
    __half2 h0 = __floats2half2_rn(v.x, v.y);
    __half2 h1 = __floats2half2_rn(v.z, v.w);
    uint2 pk = { *(unsigned*)&h0, *(unsigned*)&h1 };
    ((uint2*)dst)[i] = pk;
}

// ---------------- PE add, vectorized ----------------
__global__ void __launch_bounds__(256)
pe_add_kernel(const float* __restrict__ x, float* __restrict__ out,
              __half* __restrict__ outh) {
    int i = blockIdx.x * blockDim.x + threadIdx.x;
    if (i >= TT*EE/4) return;
    int e4 = (i & (EE/4 - 1)) * 4;
    int b = (i / (EE/4)) & (BB - 1);
    float4 v = ((const float4*)x)[i];
    float pe[4];
#pragma unroll
    for (int j = 0; j < 4; j++) {
        int e = e4 + j;
        float ef = (e & 1) ? (float)(e + 1) : (float)e;
        float freq = __expf(-ef * (9.210340371976184f / 512.0f));
        float arg = (float)(b + 1) * freq;
        pe[j] = (e & 1) ? cosf(arg) : sinf(arg);
    }
    float4 o = {v.x + pe[0], v.y + pe[1], v.z + pe[2], v.w + pe[3]};
    ((float4*)out)[i] = o;
    __half2 h0 = __floats2half2_rn(o.x, o.y);
    __half2 h1 = __floats2half2_rn(o.z, o.w);
    uint2 pk = { *(unsigned*)&h0, *(unsigned*)&h1 };
    ((uint2*)outh)[i] = pk;
}

// ---------------- fp16 GEMM, 3-stage cp.async, ldmatrix -----------------
#define HSTRIDE 40
#define HSTAGE  (128*HSTRIDE)

template<int GELU, int HALF_OUT>
__global__ void __launch_bounds__(256)
gemm_h(const __half* __restrict__ A, const __half* __restrict__ W,
       const float* __restrict__ bias, float* __restrict__ Cf,
       __half* __restrict__ Ch, int N, int K) {
    extern __shared__ __half smh[];
    __half* As_ = smh;
    __half* Bs_ = smh + 3*HSTAGE;

    const int tid = threadIdx.x, lane = tid & 31, warp = tid >> 5;
    const int g = lane >> 2, t = lane & 3;
    const int wm = warp >> 2, wn = warp & 3;
    const int bRow = blockIdx.y * 128, bCol = blockIdx.x * 128;
    const int lr = tid >> 1, ho = (tid & 1) * 16;
    const int l15 = lane & 15, lhi8 = (lane >> 4) << 3;
    const int bn = (lane & 7) + ((lane & 16) >> 1);
    const int bk = lane & 8;

    const __half* Ap = A + (size_t)(bRow + lr) * K + ho;
    const __half* Wp = W + (size_t)(bCol + lr) * K + ho;

    float c[4][4][4];
#pragma unroll
    for (int ma = 0; ma < 4; ma++)
#pragma unroll
        for (int nf = 0; nf < 4; nf++)
#pragma unroll
            for (int q = 0; q < 4; q++) c[ma][nf][q] = 0.0f;

    const int KT = K >> 5;

    auto issue = [&](int s, int kt) {
        __half* as = As_ + s*HSTAGE + lr*HSTRIDE + ho;
        __half* bs = Bs_ + s*HSTAGE + lr*HSTRIDE + ho;
        cp16(as,     Ap + kt*32);
        cp16(as + 8, Ap + kt*32 + 8);
        cp16(bs,     Wp + kt*32);
        cp16(bs + 8, Wp + kt*32 + 8);
    };

    issue(0, 0); CP_COMMIT();
    issue(1, 1); CP_COMMIT();
    CP_WAIT1();
    __syncthreads();

    for (int kt = 0; kt < KT; kt++) {
        const int cur = kt % 3;
        const __half* As = As_ + cur*HSTAGE;
        const __half* Bs = Bs_ + cur*HSTAGE;

#pragma unroll
        for (int kb = 0; kb < 2; kb++) {
            uint4 av[4];
#pragma unroll
            for (int ma = 0; ma < 4; ma++)
                av[ma] = ldsm4(&As[(wm*64 + ma*16 + l15)*HSTRIDE + kb*16 + lhi8]);
            unsigned bf[4][2];
#pragma unroll
            for (int np = 0; np < 2; np++) {
                uint4 bv = ldsm4(&Bs[(wn*32 + np*16 + bn)*HSTRIDE + kb*16 + bk]);
                bf[2*np][0]   = bv.x; bf[2*np][1]   = bv.y;
                bf[2*np+1][0] = bv.z; bf[2*np+1][1] = bv.w;
            }
#pragma unroll
            for (int ma = 0; ma < 4; ma++)
#pragma unroll
                for (int nf = 0; nf < 4; nf++)
                    MMA16(c[ma][nf], av[ma].x, av[ma].y, av[ma].z, av[ma].w,
                          bf[nf][0], bf[nf][1]);
        }

        if (kt + 2 < KT) issue((kt + 2) % 3, kt + 2);
        CP_COMMIT();
        CP_WAIT1();
        __syncthreads();
    }

#pragma unroll
    for (int ma = 0; ma < 4; ma++) {
#pragma unroll
        for (int nf = 0; nf < 4; nf++) {
            int col = bCol + wn*32 + nf*8 + 2*t;
            int row = bRow + wm*64 + ma*16 + g;
            float b0 = bias[col], b1 = bias[col+1];
            float v0 = c[ma][nf][0]+b0, v1 = c[ma][nf][1]+b1;
            float v2 = c[ma][nf][2]+b0, v3 = c[ma][nf][3]+b1;
            if (GELU) { v0=gelu_exact(v0); v1=gelu_exact(v1);
                        v2=gelu_exact(v2); v3=gelu_exact(v3); }
            if (HALF_OUT) {
                *(__half2*)&Ch[(size_t)row*N + col]     = __floats2half2_rn(v0, v1);
                *(__half2*)&Ch[(size_t)(row+8)*N + col] = __floats2half2_rn(v2, v3);
            } else {
                float2 p0 = {v0,v1}, p1 = {v2,v3};
                *(float2*)&Cf[(size_t)row*N + col]     = p0;
                *(float2*)&Cf[(size_t)(row+8)*N + col] = p1;
            }
        }
    }
}

// ---------------- fp16 flash attention, P-in-registers, base-2 softmax ----
// grid (L/128, B*H), 256 thr = 8 warps, warp = 16 q-rows.
// smem: Qs[128][72] (prescaled by 0.125*log2e), Ks[2][64][72], Vs[2][64][72].
#define ASTRIDE 72
#define QKSCALE 0.18033688011112042f   // 0.125 * log2(e)
__global__ void __launch_bounds__(256)
attn_h(const __half* __restrict__ qkv, __half* __restrict__ outh) {
    extern __shared__ __half smh[];
    __half* Qs = smh;                       // 128*72
    __half* Ks = smh + 128*ASTRIDE;         // 2*64*72
    __half* Vs = Ks + 2*64*ASTRIDE;         // 2*64*72

    const int tid = threadIdx.x, lane = tid & 31, warp = tid >> 5;
    const int g = lane >> 2, t = lane & 3;
    const int q0 = blockIdx.x * 128;
    const int b = blockIdx.y >> 3, h = blockIdx.y & 7;
    const int w16 = warp * 16;
    const int l15 = lane & 15, lhi8 = (lane >> 4) << 3;
    const int bn = (lane & 7) + ((lane & 16) >> 1);
    const int bk = lane & 8;
    const size_t qoff = h*64, koff = 512 + h*64, voff = 1024 + h*64;

    // Q tile, folded scale (fp32 multiply, repack)
    for (int i = tid; i < 128*8; i += 256) {
        int r = i >> 3, c = (i & 7) * 8;
        uint4 v = *(const uint4*)&qkv[((size_t)((q0+r)*BB + b))*1536 + qoff + c];
        __half2* hp = (__half2*)&v;
        uint4 w;
        unsigned* wp = (unsigned*)&w;
#pragma unroll
        for (int j = 0; j < 4; j++) {
            float2 f = __half22float2(hp[j]);
            __half2 sh = __floats2half2_rn(f.x * QKSCALE, f.y * QKSCALE);
            wp[j] = *(unsigned*)&sh;
        }
        *(uint4*)&Qs[r*ASTRIDE + c] = w;
    }

    auto issue = [&](int s, int kt) {
        int k0 = kt * 64;
#pragma unroll
        for (int j = 0; j < 4; j++) {
            int i = tid + j*256;
            int kv = i >> 9, r = (i >> 3) & 63, c = (i & 7) * 8;
            __half* dst = (kv ? Vs : Ks) + s*64*ASTRIDE + r*ASTRIDE + c;
            const __half* src = qkv + ((size_t)((k0+r)*BB + b))*1536 + (kv ? voff : koff) + c;
            cp16(dst, src);
        }
    };

    issue(0, 0); CP_COMMIT();

    float m_[2] = {-1e30f, -1e30f}, l_[2] = {0.0f, 0.0f};
    float o[8][4];
#pragma unroll
    for (int nf = 0; nf < 8; nf++)
#pragma unroll
        for (int q = 0; q < 4; q++) o[nf][q] = 0.0f;

    const int NT = LL/64;
    for (int kt = 0; kt < NT; kt++) {
        const int cur = kt & 1;
        if (kt + 1 < NT) issue(cur ^ 1, kt + 1);
        CP_COMMIT();
        CP_WAIT1();
        __syncthreads();

        const __half* Kc = Ks + cur*64*ASTRIDE;
        const __half* Vc = Vs + cur*64*ASTRIDE;

        // S' = (Q*c) K^T  (base-2 log-scores)
        float s_[8][4];
#pragma unroll
        for (int nf = 0; nf < 8; nf++)
#pragma unroll
            for (int q = 0; q < 4; q++) s_[nf][q] = 0.0f;

#pragma unroll
        for (int kb = 0; kb < 4; kb++) {
            uint4 av = ldsm4(&Qs[(w16 + l15)*ASTRIDE + kb*16 + lhi8]);
            unsigned bf[8][2];
#pragma unroll
            for (int np = 0; np < 4; np++) {
                uint4 bv = ldsm4(&Kc[(np*16 + bn)*ASTRIDE + kb*16 + bk]);
                bf[2*np][0]   = bv.x; bf[2*np][1]   = bv.y;
                bf[2*np+1][0] = bv.z; bf[2*np+1][1] = bv.w;
            }
#pragma unroll
            for (int nf = 0; nf < 8; nf++)
                MMA16(s_[nf], av.x, av.y, av.z, av.w, bf[nf][0], bf[nf][1]);
        }

        // base-2 online softmax (rows g, g+8; reduce over 4-lane t-group)
        float sc[2];
#pragma unroll
        for (int hf = 0; hf < 2; hf++) {
            float mx = -1e30f;
#pragma unroll
            for (int nf = 0; nf < 8; nf++)
                mx = fmaxf(mx, fmaxf(s_[nf][2*hf], s_[nf][2*hf+1]));
            mx = fmaxf(mx, __shfl_xor_sync(0xffffffffu, mx, 1));
            mx = fmaxf(mx, __shfl_xor_sync(0xffffffffu, mx, 2));
            float mn = fmaxf(m_[hf], mx);
            sc[hf] = ex2f(m_[hf] - mn);
            float rs = 0.0f;
#pragma unroll
            for (int nf = 0; nf < 8; nf++) {
                s_[nf][2*hf]   = ex2f(s_[nf][2*hf]   - mn);
                s_[nf][2*hf+1] = ex2f(s_[nf][2*hf+1] - mn);
                rs += s_[nf][2*hf] + s_[nf][2*hf+1];
            }
            rs += __shfl_xor_sync(0xffffffffu, rs, 1);
            rs += __shfl_xor_sync(0xffffffffu, rs, 2);
            l_[hf] = l_[hf] * sc[hf] + rs;
            m_[hf] = mn;
        }
        bool need = (sc[0] != 1.0f) || (sc[1] != 1.0f);
        if (__any_sync(0xffffffffu, need)) {
#pragma unroll
            for (int nf = 0; nf < 8; nf++) {
                o[nf][0] *= sc[0]; o[nf][1] *= sc[0];
                o[nf][2] *= sc[1]; o[nf][3] *= sc[1];
            }
        }

        // O += P V   (P packed directly from S fragments — no smem round trip)
#pragma unroll
        for (int kb = 0; kb < 4; kb++) {
            __half2 ah0 = __floats2half2_rn(s_[2*kb][0],   s_[2*kb][1]);
            __half2 ah1 = __floats2half2_rn(s_[2*kb][2],   s_[2*kb][3]);
            __half2 ah2 = __floats2half2_rn(s_[2*kb+1][0], s_[2*kb+1][1]);
            __half2 ah3 = __floats2half2_rn(s_[2*kb+1][2], s_[2*kb+1][3]);
            unsigned a0 = *(unsigned*)&ah0, a1 = *(unsigned*)&ah1;
            unsigned a2 = *(unsigned*)&ah2, a3 = *(unsigned*)&ah3;
            unsigned bf[8][2];
#pragma unroll
            for (int df = 0; df < 4; df++) {
                uint4 bv = ldsm4t(&Vc[(kb*16 + l15)*ASTRIDE + df*16 + lhi8]);
                bf[2*df][0]   = bv.x; bf[2*df][1]   = bv.y;
                bf[2*df+1][0] = bv.z; bf[2*df+1][1] = bv.w;
            }
#pragma unroll
            for (int nf = 0; nf < 8; nf++)
                MMA16(o[nf], a0, a1, a2, a3, bf[nf][0], bf[nf][1]);
        }
        __syncthreads();   // stage safe to overwrite next iteration
    }

#pragma unroll
    for (int hf = 0; hf < 2; hf++) {
        float inv = 1.0f / l_[hf];
        int row = q0 + w16 + g + 8*hf;
        size_t base = ((size_t)row*BB + b)*512 + h*64;
#pragma unroll
        for (int nf = 0; nf < 8; nf++)
            *(__half2*)&outh[base + nf*8 + 2*t] =
                __floats2half2_rn(o[nf][2*hf]*inv, o[nf][2*hf+1]*inv);
    }
}

// ---------------- residual add + layernorm, vectorized ----------------
template<int WH>
__global__ void __launch_bounds__(128)
add_ln_kernel(const float* __restrict__ a, const float* __restrict__ r,
              const float* __restrict__ g, const float* __restrict__ beta,
              float* __restrict__ out, __half* __restrict__ outh) {
    __shared__ float red[4];
    int t = blockIdx.x;
    int tid = threadIdx.x;
    float4 va = ((const float4*)(a + (size_t)t*EE))[tid];
    float4 vr = ((const float4*)(r + (size_t)t*EE))[tid];
    float4 v = {va.x+vr.x, va.y+vr.y, va.z+vr.z, va.w+vr.w};

    float sum = v.x + v.y + v.z + v.w;
#pragma unroll
    for (int off = 16; off > 0; off >>= 1)
        sum += __shfl_xor_sync(0xffffffffu, sum, off);
    if ((tid & 31) == 0) red[tid >> 5] = sum;
    __syncthreads();
    float mu = (red[0] + red[1] + red[2] + red[3]) * (1.0f / 512.0f);
    __syncthreads();

    float4 d = {v.x-mu, v.y-mu, v.z-mu, v.w-mu};
    float sq = d.x*d.x + d.y*d.y + d.z*d.z + d.w*d.w;
#pragma unroll
    for (int off = 16; off > 0; off >>= 1)
        sq += __shfl_xor_sync(0xffffffffu, sq, off);
    if ((tid & 31) == 0) red[tid >> 5] = sq;
    __syncthreads();
    float rstd = rsqrtf((red[0]+red[1]+red[2]+red[3]) * (1.0f/512.0f) + 1e-5f);

    float4 gg = ((const float4*)g)[tid];
    float4 bb = ((const float4*)beta)[tid];
    float4 o = {d.x*rstd*gg.x + bb.x, d.y*rstd*gg.y + bb.y,
                d.z*rstd*gg.z + bb.z, d.w*rstd*gg.w + bb.w};
    ((float4*)(out + (size_t)t*EE))[tid] = o;
    if (WH) {
        __half2 h0 = __floats2half2_rn(o.x, o.y);
        __half2 h1 = __floats2half2_rn(o.z, o.w);
        uint2 pk = { *(unsigned*)&h0, *(unsigned*)&h1 };
        ((uint2*)(outh + (size_t)t*EE))[tid] = pk;
    }
}

// ---------------- launch ----------------
extern "C" void kernel_launch(void* const* d_in, const int* in_sizes, int n_in,
                              void* d_out, int out_size) {
    const float* x     = (const float*)d_in[0];
    const float* in_w  = (const float*)d_in[1];
    const float* in_b  = (const float*)d_in[2];
    const float* out_w = (const float*)d_in[3];
    const float* out_b = (const float*)d_in[4];
    const float* w1    = (const float*)d_in[5];
    const float* b1    = (const float*)d_in[6];
    const float* w2    = (const float*)d_in[7];
    const float* b2    = (const float*)d_in[8];
    const float* ln_g  = (const float*)d_in[9];
    const float* ln_b  = (const float*)d_in[10];
    float* out = (float*)d_out;

    float *x0, *proj, *x1, *ff;
    __half *x0h, *qkvh, *atth, *x1h, *hh, *wh;
    cudaGetSymbolAddress((void**)&x0,   g_x0);
    cudaGetSymbolAddress((void**)&proj, g_proj);
    cudaGetSymbolAddress((void**)&x1,   g_x1);
    cudaGetSymbolAddress((void**)&ff,   g_ff);
    cudaGetSymbolAddress((void**)&x0h,  g_x0h);
    cudaGetSymbolAddress((void**)&qkvh, g_qkvh);
    cudaGetSymbolAddress((void**)&atth, g_atth);
    cudaGetSymbolAddress((void**)&x1h,  g_x1h);
    cudaGetSymbolAddress((void**)&hh,   g_hh);
    cudaGetSymbolAddress((void**)&wh,   g_wh);

    const int gemm_smem = 6 * HSTAGE * (int)sizeof(__half);
    const int attn_smem = (128 + 4*64) * ASTRIDE * (int)sizeof(__half);   // 55296
    cudaFuncSetAttribute(gemm_h<0,0>, cudaFuncAttributeMaxDynamicSharedMemorySize, gemm_smem);
    cudaFuncSetAttribute(gemm_h<0,1>, cudaFuncAttributeMaxDynamicSharedMemorySize, gemm_smem);
    cudaFuncSetAttribute(gemm_h<1,1>, cudaFuncAttributeMaxDynamicSharedMemorySize, gemm_smem);
    cudaFuncSetAttribute(attn_h, cudaFuncAttributeMaxDynamicSharedMemorySize, attn_smem);

    f2h_all<<<(786432 + 255)/256, 256>>>(in_w, out_w, w1, w2, wh);
    pe_add_kernel<<<(TT*EE/4 + 255)/256, 256>>>(x, x0, x0h);
    gemm_h<0,1><<<dim3(1536/128, TT/128), 256, gemm_smem>>>(x0h, wh + WOFF_IN, in_b, nullptr, qkvh, 1536, 512);
    attn_h<<<dim3(LL/128, BB*HH), 256, attn_smem>>>(qkvh, atth);
    gemm_h<0,0><<<dim3(512/128, TT/128), 256, gemm_smem>>>(atth, wh + WOFF_OUT, out_b, proj, nullptr, 512, 512);
    add_ln_kernel<1><<<TT, 128>>>(proj, x0, ln_g, ln_b, x1, x1h);
    gemm_h<1,1><<<dim3(2048/128, TT/128), 256, gemm_smem>>>(x1h, wh + WOFF_W1, b1, nullptr, hh, 2048, 512);
    gemm_h<0,0><<<dim3(512/128, TT/128), 256, gemm_smem>>>(hh, wh + WOFF_W2, b2, ff, nullptr, 512, 2048);
    add_ln_kernel<0><<<TT, 128>>>(ff, x1, ln_g, ln_b, out, nullptr);
}